// round 6
// baseline (speedup 1.0000x reference)
#include <cuda_runtime.h>
#include <cuda_bf16.h>
#include <cstdint>
#include <math.h>

// ---------------------------------------------------------------------------
// DeepseekV2 MoE.
//  - x + shared weights: one-time hi/lo bf16 plane split (reused many times).
//  - Expert weights: read fp32 ONCE inside routed GEMMs, convert to hi/lo in
//    the smem producer path (128-row M tiles -> single pass over weights).
//  - All GEMMs: m16n8k16 bf16 MMA, 3-term hi/lo split, ldmatrix fragments.
// ---------------------------------------------------------------------------

#define T_TOK   1024
#define H_DIM   1024
#define E_EXP   64
#define I_DIM   512
#define TOPK    6
#define NGROUP  8
#define TKG     3
#define CAP     256
#define A_TOT   (T_TOK * TOPK)
#define SCALE_F 2.5f
#define GUP_COLS (2 * I_DIM)
#define SH_ACT   1024
#define SH_GUP   2048

#define KC 32          // k-chunk
#define SA 40          // A smem stride
#define SB 72          // B smem stride

// ------------------------------- scratch -----------------------------------
__device__ float g_w[A_TOT];
__device__ int   g_eidx[A_TOT];
__device__ int   g_counts[E_EXP];
__device__ int   g_list[E_EXP * CAP];
__device__ int   g_keep[A_TOT];

__device__ __nv_bfloat16 g_xs_h[T_TOK * H_DIM];
__device__ __nv_bfloat16 g_xs_l[T_TOK * H_DIM];
__device__ __nv_bfloat16 g_wsgu_h[H_DIM * SH_GUP];
__device__ __nv_bfloat16 g_wsgu_l[H_DIM * SH_GUP];
__device__ __nv_bfloat16 g_wsd_h[SH_ACT * H_DIM];
__device__ __nv_bfloat16 g_wsd_l[SH_ACT * H_DIM];
__device__ __nv_bfloat16 g_acts_h[T_TOK * SH_ACT];
__device__ __nv_bfloat16 g_acts_l[T_TOK * SH_ACT];
__device__ __nv_bfloat16 g_actr_h[(size_t)E_EXP * CAP * I_DIM];
__device__ __nv_bfloat16 g_actr_l[(size_t)E_EXP * CAP * I_DIM];
__device__ float g_ybuf[(size_t)A_TOT * H_DIM];

// ------------------------------- helpers -----------------------------------
__device__ __forceinline__ unsigned pack2(__nv_bfloat16 a, __nv_bfloat16 b) {
    __nv_bfloat162 t = __halves2bfloat162(a, b);
    return *(unsigned*)&t;
}

__device__ __forceinline__ void f2hl2(float x, float y, unsigned& h, unsigned& l) {
    __nv_bfloat16 h0 = __float2bfloat16(x), h1 = __float2bfloat16(y);
    __nv_bfloat16 l0 = __float2bfloat16(x - __bfloat162float(h0));
    __nv_bfloat16 l1 = __float2bfloat16(y - __bfloat162float(h1));
    h = pack2(h0, h1);
    l = pack2(l0, l1);
}

__device__ __forceinline__ void mma_bf16(float c[4],
    unsigned a0, unsigned a1, unsigned a2, unsigned a3,
    unsigned b0, unsigned b1)
{
    asm volatile(
        "mma.sync.aligned.m16n8k16.row.col.f32.bf16.bf16.f32 "
        "{%0,%1,%2,%3}, {%4,%5,%6,%7}, {%8,%9}, {%0,%1,%2,%3};"
        : "+f"(c[0]), "+f"(c[1]), "+f"(c[2]), "+f"(c[3])
        : "r"(a0), "r"(a1), "r"(a2), "r"(a3), "r"(b0), "r"(b1));
}

__device__ __forceinline__ void ldsm4(unsigned* r, uint32_t addr) {
    asm volatile("ldmatrix.sync.aligned.m8n8.x4.shared.b16 {%0,%1,%2,%3}, [%4];"
        : "=r"(r[0]), "=r"(r[1]), "=r"(r[2]), "=r"(r[3]) : "r"(addr));
}
__device__ __forceinline__ void ldsm4t(unsigned* r, uint32_t addr) {
    asm volatile("ldmatrix.sync.aligned.m8n8.x4.trans.shared.b16 {%0,%1,%2,%3}, [%4];"
        : "=r"(r[0]), "=r"(r[1]), "=r"(r[2]), "=r"(r[3]) : "r"(addr));
}

// ------------------------------- split -------------------------------------
__global__ __launch_bounds__(256) void split_kernel(
    const float4* __restrict__ src, uint2* __restrict__ hi, uint2* __restrict__ lo, int n4)
{
    int i = blockIdx.x * 256 + threadIdx.x;
    if (i >= n4) return;
    float4 v = src[i];
    unsigned h01, l01, h23, l23;
    f2hl2(v.x, v.y, h01, l01);
    f2hl2(v.z, v.w, h23, l23);
    hi[i] = make_uint2(h01, h23);
    lo[i] = make_uint2(l01, l23);
}

// ------------------------------- router ------------------------------------
__global__ __launch_bounds__(256) void router_kernel(
    const float* __restrict__ x, const float* __restrict__ gw,
    const float* __restrict__ bias)
{
    __shared__ float xs[H_DIM];
    __shared__ float lg[E_EXP];
    const int t = blockIdx.x, tid = threadIdx.x;

    *(float4*)&xs[tid * 4] = *(const float4*)(x + (size_t)t * H_DIM + tid * 4);
    __syncthreads();

    if (tid < E_EXP) {
        float acc = 0.f;
#pragma unroll 8
        for (int h = 0; h < H_DIM; h++)
            acc += xs[h] * gw[h * E_EXP + tid];
        lg[tid] = acc;
    }
    __syncthreads();

    if (tid == 0) {
        float sc[E_EXP], s[E_EXP];
#pragma unroll
        for (int e = 0; e < E_EXP; e++) {
            sc[e] = 1.f / (1.f + expf(-lg[e]));
            s[e]  = sc[e] + bias[e];
        }
        float gs[NGROUP];
#pragma unroll
        for (int g = 0; g < NGROUP; g++) {
            float m1 = -INFINITY, m2 = -INFINITY;
            for (int j = 0; j < E_EXP / NGROUP; j++) {
                float v = s[g * (E_EXP / NGROUP) + j];
                if (v > m1) { m2 = m1; m1 = v; }
                else if (v > m2) { m2 = v; }
            }
            gs[g] = m1 + m2;
        }
        bool gsel[NGROUP];
#pragma unroll
        for (int g = 0; g < NGROUP; g++) gsel[g] = false;
        for (int it = 0; it < TKG; it++) {
            int bi = -1; float bv = -INFINITY;
            for (int g = 0; g < NGROUP; g++)
                if (!gsel[g] && gs[g] > bv) { bv = gs[g]; bi = g; }
            gsel[bi] = true;
        }
        bool used[E_EXP];
#pragma unroll
        for (int e = 0; e < E_EXP; e++) used[e] = false;
        int   idx[TOPK];
        float wv[TOPK];
        float wsum = 0.f;
        for (int k = 0; k < TOPK; k++) {
            int bi = -1; float bv = -INFINITY;
            for (int e = 0; e < E_EXP; e++) {
                if (!gsel[e / (E_EXP / NGROUP)] || used[e]) continue;
                if (s[e] > bv) { bv = s[e]; bi = e; }
            }
            used[bi] = true;
            idx[k] = bi;
            wv[k]  = sc[bi];
            wsum  += sc[bi];
        }
        float inv = 1.f / wsum;
        for (int k = 0; k < TOPK; k++) {
            g_w[t * TOPK + k]    = wv[k] * inv;
            g_eidx[t * TOPK + k] = idx[k];
        }
    }
}

// ------------------------------ dispatch -----------------------------------
__global__ __launch_bounds__(256) void dispatch_kernel()
{
    const int e = blockIdx.x, tid = threadIdx.x;
    const int lane = tid & 31, wid = tid >> 5;
    __shared__ int warp_tot[8];
    int base = 0;
    for (int chunk = 0; chunk < A_TOT; chunk += 256) {
        int a = chunk + tid;
        int m = (a < A_TOT && g_eidx[a] == e) ? 1 : 0;
        unsigned bal = __ballot_sync(0xffffffffu, m);
        if (lane == 0) warp_tot[wid] = __popc(bal);
        __syncthreads();
        int woff = 0, tot = 0;
#pragma unroll
        for (int i = 0; i < 8; i++) { if (i < wid) woff += warp_tot[i]; tot += warp_tot[i]; }
        if (m) {
            int pos = base + woff + __popc(bal & ((1u << lane) - 1u));
            if (pos < CAP) g_list[e * CAP + pos] = a;
            g_keep[a] = (pos < CAP) ? 1 : 0;
        }
        base += tot;
        __syncthreads();
    }
    if (tid == 0) g_counts[e] = base < CAP ? base : CAP;
}

// ===========================================================================
// Shared-expert GEMMs: 64x64 tile, 256 thr = 8 warps (4M x 2N).
// ===========================================================================

__global__ __launch_bounds__(256) void shared_gateup_tc()
{
    __shared__ __align__(16) __nv_bfloat16 sAh[64 * SA], sAl[64 * SA];
    __shared__ __align__(16) __nv_bfloat16 sGh[KC * SB], sGl[KC * SB];
    __shared__ __align__(16) __nv_bfloat16 sUh[KC * SB], sUl[KC * SB];

    const int tid = threadIdx.x, lane = tid & 31, wid = tid >> 5;
    const int gid = lane >> 2, tig = lane & 3;
    const int wm = wid & 3, wn = wid >> 2;
    const int rb = blockIdx.y * 64, cb = blockIdx.x * 64;

    const int ar = tid >> 2, ac8 = (tid & 3) * 8;
    const int bk = tid >> 3, bn8 = (tid & 7) * 8;

    const __nv_bfloat16* aH = g_xs_h + (size_t)(rb + ar) * H_DIM + ac8;
    const __nv_bfloat16* aL = g_xs_l + (size_t)(rb + ar) * H_DIM + ac8;
    const __nv_bfloat16* gH = g_wsgu_h + (size_t)bk * SH_GUP + cb + bn8;
    const __nv_bfloat16* gL = g_wsgu_l + (size_t)bk * SH_GUP + cb + bn8;
    const __nv_bfloat16* uH = gH + SH_ACT;
    const __nv_bfloat16* uL = gL + SH_ACT;

    const uint32_t aBase = (uint32_t)((((wm * 16 + (lane & 15)) * SA) + (lane >> 4) * 8) * 2);
    uint32_t aOffH = (uint32_t)__cvta_generic_to_shared(sAh) + aBase;
    uint32_t aOffL = (uint32_t)__cvta_generic_to_shared(sAl) + aBase;
    const int mB = lane >> 3;
    const uint32_t bBase = (uint32_t)(((((mB & 1) * 8 + (lane & 7)) * SB) + wn * 32 + (mB >> 1) * 8) * 2);
    uint32_t gOffH = (uint32_t)__cvta_generic_to_shared(sGh) + bBase;
    uint32_t gOffL = (uint32_t)__cvta_generic_to_shared(sGl) + bBase;
    uint32_t uOffH = (uint32_t)__cvta_generic_to_shared(sUh) + bBase;
    uint32_t uOffL = (uint32_t)__cvta_generic_to_shared(sUl) + bBase;

    float accG[4][4] = {}, accU[4][4] = {};

    for (int k0 = 0; k0 < H_DIM; k0 += KC) {
        *(uint4*)&sAh[ar * SA + ac8] = *(const uint4*)(aH + k0);
        *(uint4*)&sAl[ar * SA + ac8] = *(const uint4*)(aL + k0);
        *(uint4*)&sGh[bk * SB + bn8] = *(const uint4*)(gH + (size_t)k0 * SH_GUP);
        *(uint4*)&sGl[bk * SB + bn8] = *(const uint4*)(gL + (size_t)k0 * SH_GUP);
        *(uint4*)&sUh[bk * SB + bn8] = *(const uint4*)(uH + (size_t)k0 * SH_GUP);
        *(uint4*)&sUl[bk * SB + bn8] = *(const uint4*)(uL + (size_t)k0 * SH_GUP);
        __syncthreads();
#pragma unroll
        for (int s = 0; s < 2; s++) {
            unsigned ah[4], al[4];
            ldsm4(ah, aOffH + s * 32);
            ldsm4(al, aOffL + s * 32);
            unsigned gh[8], gl[8], uh[8], ul[8];
#pragma unroll
            for (int g = 0; g < 2; g++) {
                uint32_t off = (uint32_t)(s * 16 * SB) * 2 + g * 32;
                ldsm4t(&gh[g * 4], gOffH + off);
                ldsm4t(&gl[g * 4], gOffL + off);
                ldsm4t(&uh[g * 4], uOffH + off);
                ldsm4t(&ul[g * 4], uOffL + off);
            }
#pragma unroll
            for (int t = 0; t < 4; t++) {
                int p = (t >> 1) * 4 + (t & 1) * 2;
                mma_bf16(accG[t], ah[0], ah[1], ah[2], ah[3], gh[p], gh[p + 1]);
                mma_bf16(accG[t], ah[0], ah[1], ah[2], ah[3], gl[p], gl[p + 1]);
                mma_bf16(accG[t], al[0], al[1], al[2], al[3], gh[p], gh[p + 1]);
                mma_bf16(accU[t], ah[0], ah[1], ah[2], ah[3], uh[p], uh[p + 1]);
                mma_bf16(accU[t], ah[0], ah[1], ah[2], ah[3], ul[p], ul[p + 1]);
                mma_bf16(accU[t], al[0], al[1], al[2], al[3], uh[p], uh[p + 1]);
            }
        }
        __syncthreads();
    }
    const int r0 = rb + wm * 16 + gid;
#pragma unroll
    for (int t = 0; t < 4; t++) {
        int c = cb + wn * 32 + t * 8 + tig * 2;
#pragma unroll
        for (int i = 0; i < 2; i++) {
            int r = r0 + i * 8;
            float g0 = accG[t][i * 2], u0 = accU[t][i * 2];
            float g1 = accG[t][i * 2 + 1], u1 = accU[t][i * 2 + 1];
            float a0 = (g0 / (1.f + expf(-g0))) * u0;
            float a1 = (g1 / (1.f + expf(-g1))) * u1;
            unsigned h, l;
            f2hl2(a0, a1, h, l);
            *(unsigned*)&g_acts_h[(size_t)r * SH_ACT + c] = h;
            *(unsigned*)&g_acts_l[(size_t)r * SH_ACT + c] = l;
        }
    }
}

__global__ __launch_bounds__(256) void shared_down_tc(float* __restrict__ out)
{
    __shared__ __align__(16) __nv_bfloat16 sAh[64 * SA], sAl[64 * SA];
    __shared__ __align__(16) __nv_bfloat16 sBh[KC * SB], sBl[KC * SB];

    const int tid = threadIdx.x, lane = tid & 31, wid = tid >> 5;
    const int gid = lane >> 2, tig = lane & 3;
    const int wm = wid & 3, wn = wid >> 2;
    const int rb = blockIdx.y * 64, cb = blockIdx.x * 64;

    const int ar = tid >> 2, ac8 = (tid & 3) * 8;
    const int bk = tid >> 3, bn8 = (tid & 7) * 8;

    const __nv_bfloat16* aH = g_acts_h + (size_t)(rb + ar) * SH_ACT + ac8;
    const __nv_bfloat16* aL = g_acts_l + (size_t)(rb + ar) * SH_ACT + ac8;
    const __nv_bfloat16* bH = g_wsd_h + (size_t)bk * H_DIM + cb + bn8;
    const __nv_bfloat16* bL = g_wsd_l + (size_t)bk * H_DIM + cb + bn8;

    const uint32_t aBase = (uint32_t)((((wm * 16 + (lane & 15)) * SA) + (lane >> 4) * 8) * 2);
    uint32_t aOffH = (uint32_t)__cvta_generic_to_shared(sAh) + aBase;
    uint32_t aOffL = (uint32_t)__cvta_generic_to_shared(sAl) + aBase;
    const int mB = lane >> 3;
    const uint32_t bBase = (uint32_t)(((((mB & 1) * 8 + (lane & 7)) * SB) + wn * 32 + (mB >> 1) * 8) * 2);
    uint32_t bOffH = (uint32_t)__cvta_generic_to_shared(sBh) + bBase;
    uint32_t bOffL = (uint32_t)__cvta_generic_to_shared(sBl) + bBase;

    float acc[4][4] = {};

    for (int k0 = 0; k0 < SH_ACT; k0 += KC) {
        *(uint4*)&sAh[ar * SA + ac8] = *(const uint4*)(aH + k0);
        *(uint4*)&sAl[ar * SA + ac8] = *(const uint4*)(aL + k0);
        *(uint4*)&sBh[bk * SB + bn8] = *(const uint4*)(bH + (size_t)k0 * H_DIM);
        *(uint4*)&sBl[bk * SB + bn8] = *(const uint4*)(bL + (size_t)k0 * H_DIM);
        __syncthreads();
#pragma unroll
        for (int s = 0; s < 2; s++) {
            unsigned ah[4], al[4];
            ldsm4(ah, aOffH + s * 32);
            ldsm4(al, aOffL + s * 32);
            unsigned bh[8], bl[8];
#pragma unroll
            for (int g = 0; g < 2; g++) {
                uint32_t off = (uint32_t)(s * 16 * SB) * 2 + g * 32;
                ldsm4t(&bh[g * 4], bOffH + off);
                ldsm4t(&bl[g * 4], bOffL + off);
            }
#pragma unroll
            for (int t = 0; t < 4; t++) {
                int p = (t >> 1) * 4 + (t & 1) * 2;
                mma_bf16(acc[t], ah[0], ah[1], ah[2], ah[3], bh[p], bh[p + 1]);
                mma_bf16(acc[t], ah[0], ah[1], ah[2], ah[3], bl[p], bl[p + 1]);
                mma_bf16(acc[t], al[0], al[1], al[2], al[3], bh[p], bh[p + 1]);
            }
        }
        __syncthreads();
    }
    const int r0 = rb + wm * 16 + gid;
#pragma unroll
    for (int t = 0; t < 4; t++) {
        int c = cb + wn * 32 + t * 8 + tig * 2;
        out[(size_t)(r0    ) * H_DIM + c + 0] = acc[t][0];
        out[(size_t)(r0    ) * H_DIM + c + 1] = acc[t][1];
        out[(size_t)(r0 + 8) * H_DIM + c + 0] = acc[t][2];
        out[(size_t)(r0 + 8) * H_DIM + c + 1] = acc[t][3];
    }
}

// ===========================================================================
// Routed GEMMs: 128x64 tile, 512 thr = 16 warps (8M x 2N).
// Expert weights read as fp32 ONCE, converted to hi/lo in producer path.
// ===========================================================================

__global__ __launch_bounds__(512) void routed_gateup_tc(
    const float* __restrict__ Wall /*[E,H,1024] fp32*/)
{
    const int e = blockIdx.z;
    const int cnt = g_counts[e];
    const int r0b = blockIdx.y * 128;
    if (r0b >= cnt) return;

    __shared__ __align__(16) __nv_bfloat16 sAh[128 * SA], sAl[128 * SA];
    __shared__ __align__(16) __nv_bfloat16 sGh[KC * SB], sGl[KC * SB];
    __shared__ __align__(16) __nv_bfloat16 sUh[KC * SB], sUl[KC * SB];

    const int tid = threadIdx.x, lane = tid & 31, wid = tid >> 5;
    const int gid = lane >> 2, tig = lane & 3;
    const int wm = wid & 7, wn = wid >> 3;
    const int cb = blockIdx.x * 64;

    // A producer: 512 thr cover 128 rows x 32 cols (8 bf16 per thread)
    const int ar = tid >> 2, ac8 = (tid & 3) * 8;
    // B producer: 512 thr cover 32 k-rows x 64 cols fp32 (4 floats per thread)
    const int bk = tid >> 4, bc4 = (tid & 15) * 4;

    int tok = 0;
    {
        int r = r0b + ar;
        if (r < cnt) tok = g_list[e * CAP + r] / TOPK;
    }
    const __nv_bfloat16* aH = g_xs_h + (size_t)tok * H_DIM + ac8;
    const __nv_bfloat16* aL = g_xs_l + (size_t)tok * H_DIM + ac8;
    const float* gW = Wall + (size_t)e * H_DIM * GUP_COLS + (size_t)bk * GUP_COLS + cb + bc4;
    const float* uW = gW + I_DIM;

    const uint32_t aBase = (uint32_t)((((wm * 16 + (lane & 15)) * SA) + (lane >> 4) * 8) * 2);
    uint32_t aOffH = (uint32_t)__cvta_generic_to_shared(sAh) + aBase;
    uint32_t aOffL = (uint32_t)__cvta_generic_to_shared(sAl) + aBase;
    const int mB = lane >> 3;
    const uint32_t bBase = (uint32_t)(((((mB & 1) * 8 + (lane & 7)) * SB) + wn * 32 + (mB >> 1) * 8) * 2);
    uint32_t gOffH = (uint32_t)__cvta_generic_to_shared(sGh) + bBase;
    uint32_t gOffL = (uint32_t)__cvta_generic_to_shared(sGl) + bBase;
    uint32_t uOffH = (uint32_t)__cvta_generic_to_shared(sUh) + bBase;
    uint32_t uOffL = (uint32_t)__cvta_generic_to_shared(sUl) + bBase;

    float accG[4][4] = {}, accU[4][4] = {};

    for (int k0 = 0; k0 < H_DIM; k0 += KC) {
        *(uint4*)&sAh[ar * SA + ac8] = *(const uint4*)(aH + k0);
        *(uint4*)&sAl[ar * SA + ac8] = *(const uint4*)(aL + k0);
        {
            float4 vg = *(const float4*)(gW + (size_t)k0 * GUP_COLS);
            float4 vu = *(const float4*)(uW + (size_t)k0 * GUP_COLS);
            unsigned h01, l01, h23, l23;
            f2hl2(vg.x, vg.y, h01, l01); f2hl2(vg.z, vg.w, h23, l23);
            *(uint2*)&sGh[bk * SB + bc4] = make_uint2(h01, h23);
            *(uint2*)&sGl[bk * SB + bc4] = make_uint2(l01, l23);
            f2hl2(vu.x, vu.y, h01, l01); f2hl2(vu.z, vu.w, h23, l23);
            *(uint2*)&sUh[bk * SB + bc4] = make_uint2(h01, h23);
            *(uint2*)&sUl[bk * SB + bc4] = make_uint2(l01, l23);
        }
        __syncthreads();
#pragma unroll
        for (int s = 0; s < 2; s++) {
            unsigned ah[4], al[4];
            ldsm4(ah, aOffH + s * 32);
            ldsm4(al, aOffL + s * 32);
            unsigned gh[8], gl[8], uh[8], ul[8];
#pragma unroll
            for (int g = 0; g < 2; g++) {
                uint32_t off = (uint32_t)(s * 16 * SB) * 2 + g * 32;
                ldsm4t(&gh[g * 4], gOffH + off);
                ldsm4t(&gl[g * 4], gOffL + off);
                ldsm4t(&uh[g * 4], uOffH + off);
                ldsm4t(&ul[g * 4], uOffL + off);
            }
#pragma unroll
            for (int t = 0; t < 4; t++) {
                int p = (t >> 1) * 4 + (t & 1) * 2;
                mma_bf16(accG[t], ah[0], ah[1], ah[2], ah[3], gh[p], gh[p + 1]);
                mma_bf16(accG[t], ah[0], ah[1], ah[2], ah[3], gl[p], gl[p + 1]);
                mma_bf16(accG[t], al[0], al[1], al[2], al[3], gh[p], gh[p + 1]);
                mma_bf16(accU[t], ah[0], ah[1], ah[2], ah[3], uh[p], uh[p + 1]);
                mma_bf16(accU[t], ah[0], ah[1], ah[2], ah[3], ul[p], ul[p + 1]);
                mma_bf16(accU[t], al[0], al[1], al[2], al[3], uh[p], uh[p + 1]);
            }
        }
        __syncthreads();
    }
    const int rw = wm * 16 + gid;
#pragma unroll
    for (int t = 0; t < 4; t++) {
        int c = cb + wn * 32 + t * 8 + tig * 2;
#pragma unroll
        for (int i = 0; i < 2; i++) {
            int r = r0b + rw + i * 8;
            if (r < cnt) {
                float g0 = accG[t][i * 2], u0 = accU[t][i * 2];
                float g1 = accG[t][i * 2 + 1], u1 = accU[t][i * 2 + 1];
                float a0 = (g0 / (1.f + expf(-g0))) * u0;
                float a1 = (g1 / (1.f + expf(-g1))) * u1;
                unsigned h, l;
                f2hl2(a0, a1, h, l);
                *(unsigned*)&g_actr_h[((size_t)e * CAP + r) * I_DIM + c] = h;
                *(unsigned*)&g_actr_l[((size_t)e * CAP + r) * I_DIM + c] = l;
            }
        }
    }
}

__global__ __launch_bounds__(512) void routed_down_tc(
    const float* __restrict__ Wall /*[E,512,1024] fp32*/)
{
    const int e = blockIdx.z;
    const int cnt = g_counts[e];
    const int r0b = blockIdx.y * 128;
    if (r0b >= cnt) return;

    __shared__ __align__(16) __nv_bfloat16 sAh[128 * SA], sAl[128 * SA];
    __shared__ __align__(16) __nv_bfloat16 sBh[KC * SB], sBl[KC * SB];

    const int tid = threadIdx.x, lane = tid & 31, wid = tid >> 5;
    const int gid = lane >> 2, tig = lane & 3;
    const int wm = wid & 7, wn = wid >> 3;
    const int cb = blockIdx.x * 64;

    const int ar = tid >> 2, ac8 = (tid & 3) * 8;
    const int bk = tid >> 4, bc4 = (tid & 15) * 4;

    const __nv_bfloat16* aH = g_actr_h + ((size_t)e * CAP + (r0b + ar)) * I_DIM + ac8;
    const __nv_bfloat16* aL = g_actr_l + ((size_t)e * CAP + (r0b + ar)) * I_DIM + ac8;
    const float* bW = Wall + (size_t)e * I_DIM * H_DIM + (size_t)bk * H_DIM + cb + bc4;

    const uint32_t aBase = (uint32_t)((((wm * 16 + (lane & 15)) * SA) + (lane >> 4) * 8) * 2);
    uint32_t aOffH = (uint32_t)__cvta_generic_to_shared(sAh) + aBase;
    uint32_t aOffL = (uint32_t)__cvta_generic_to_shared(sAl) + aBase;
    const int mB = lane >> 3;
    const uint32_t bBase = (uint32_t)(((((mB & 1) * 8 + (lane & 7)) * SB) + wn * 32 + (mB >> 1) * 8) * 2);
    uint32_t bOffH = (uint32_t)__cvta_generic_to_shared(sBh) + bBase;
    uint32_t bOffL = (uint32_t)__cvta_generic_to_shared(sBl) + bBase;

    float acc[4][4] = {};

    for (int k0 = 0; k0 < I_DIM; k0 += KC) {
        *(uint4*)&sAh[ar * SA + ac8] = *(const uint4*)(aH + k0);
        *(uint4*)&sAl[ar * SA + ac8] = *(const uint4*)(aL + k0);
        {
            float4 vb = *(const float4*)(bW + (size_t)k0 * H_DIM);
            unsigned h01, l01, h23, l23;
            f2hl2(vb.x, vb.y, h01, l01); f2hl2(vb.z, vb.w, h23, l23);
            *(uint2*)&sBh[bk * SB + bc4] = make_uint2(h01, h23);
            *(uint2*)&sBl[bk * SB + bc4] = make_uint2(l01, l23);
        }
        __syncthreads();
#pragma unroll
        for (int s = 0; s < 2; s++) {
            unsigned ah[4], al[4];
            ldsm4(ah, aOffH + s * 32);
            ldsm4(al, aOffL + s * 32);
            unsigned bh[8], bl[8];
#pragma unroll
            for (int g = 0; g < 2; g++) {
                uint32_t off = (uint32_t)(s * 16 * SB) * 2 + g * 32;
                ldsm4t(&bh[g * 4], bOffH + off);
                ldsm4t(&bl[g * 4], bOffL + off);
            }
#pragma unroll
            for (int t = 0; t < 4; t++) {
                int p = (t >> 1) * 4 + (t & 1) * 2;
                mma_bf16(acc[t], ah[0], ah[1], ah[2], ah[3], bh[p], bh[p + 1]);
                mma_bf16(acc[t], ah[0], ah[1], ah[2], ah[3], bl[p], bl[p + 1]);
                mma_bf16(acc[t], al[0], al[1], al[2], al[3], bh[p], bh[p + 1]);
            }
        }
        __syncthreads();
    }
    const int rw = wm * 16 + gid;
#pragma unroll
    for (int t = 0; t < 4; t++) {
        int c = cb + wn * 32 + t * 8 + tig * 2;
#pragma unroll
        for (int i = 0; i < 2; i++) {
            int r = r0b + rw + i * 8;
            if (r < cnt) {
                int a = g_list[e * CAP + r];
                g_ybuf[(size_t)a * H_DIM + c + 0] = acc[t][i * 2 + 0];
                g_ybuf[(size_t)a * H_DIM + c + 1] = acc[t][i * 2 + 1];
            }
        }
    }
}

// ------------------------------- combine -----------------------------------
__global__ __launch_bounds__(256) void combine_kernel(float* __restrict__ out)
{
    const int t = blockIdx.x;
    const int h4 = threadIdx.x * 4;
    float4 o = *(float4*)(out + (size_t)t * H_DIM + h4);
    float r0 = o.x, r1 = o.y, r2 = o.z, r3 = o.w;
#pragma unroll
    for (int k = 0; k < TOPK; k++) {
        int a = t * TOPK + k;
        if (g_keep[a]) {
            float wv = g_w[a] * SCALE_F;
            float4 y = *(const float4*)(g_ybuf + (size_t)a * H_DIM + h4);
            r0 += wv * y.x; r1 += wv * y.y; r2 += wv * y.z; r3 += wv * y.w;
        }
    }
    *(float4*)(out + (size_t)t * H_DIM + h4) = make_float4(r0, r1, r2, r3);
}

// ------------------------------- launcher ----------------------------------
extern "C" void kernel_launch(void* const* d_in, const int* in_sizes, int n_in,
                              void* d_out, int out_size)
{
    const float* x          = (const float*)d_in[0];
    const float* gate_w     = (const float*)d_in[1];
    const float* e_bias     = (const float*)d_in[2];
    const float* w_gate_up  = (const float*)d_in[3];
    const float* w_down     = (const float*)d_in[4];
    const float* ws_gate_up = (const float*)d_in[5];
    const float* ws_down    = (const float*)d_in[6];
    float* out = (float*)d_out;

    __nv_bfloat16 *xs_h, *xs_l, *wsgu_h, *wsgu_l, *wsd_h, *wsd_l;
    cudaGetSymbolAddress((void**)&xs_h, g_xs_h);
    cudaGetSymbolAddress((void**)&xs_l, g_xs_l);
    cudaGetSymbolAddress((void**)&wsgu_h, g_wsgu_h);
    cudaGetSymbolAddress((void**)&wsgu_l, g_wsgu_l);
    cudaGetSymbolAddress((void**)&wsd_h, g_wsd_h);
    cudaGetSymbolAddress((void**)&wsd_l, g_wsd_l);

    auto split = [](const float* s, __nv_bfloat16* h, __nv_bfloat16* l, size_t n) {
        int n4 = (int)(n / 4);
        split_kernel<<<(n4 + 255) / 256, 256>>>((const float4*)s, (uint2*)h, (uint2*)l, n4);
    };

    split(x,          xs_h,   xs_l,   (size_t)T_TOK * H_DIM);
    split(ws_gate_up, wsgu_h, wsgu_l, (size_t)H_DIM * SH_GUP);
    split(ws_down,    wsd_h,  wsd_l,  (size_t)SH_ACT * H_DIM);

    router_kernel<<<T_TOK, 256>>>(x, gate_w, e_bias);
    dispatch_kernel<<<E_EXP, 256>>>();

    shared_gateup_tc<<<dim3(SH_ACT / 64, T_TOK / 64), 256>>>();
    shared_down_tc<<<dim3(H_DIM / 64, T_TOK / 64), 256>>>(out);
    routed_gateup_tc<<<dim3(I_DIM / 64, CAP / 128, E_EXP), 512>>>(w_gate_up);
    routed_down_tc<<<dim3(H_DIM / 64, CAP / 128, E_EXP), 512>>>(w_down);
    combine_kernel<<<T_TOK, 256>>>(out);
}

// round 7
// speedup vs baseline: 1.5075x; 1.5075x over previous
#include <cuda_runtime.h>
#include <cuda_bf16.h>
#include <cstdint>
#include <math.h>

// ---------------------------------------------------------------------------
// DeepseekV2 MoE. Round-5 GEMM pipeline (hi/lo bf16 plane splits + ldmatrix
// m16n8k16 3-term MMA) + warp-parallel router (one warp per token).
// ---------------------------------------------------------------------------

#define T_TOK   1024
#define H_DIM   1024
#define E_EXP   64
#define I_DIM   512
#define TOPK    6
#define NGROUP  8
#define TKG     3
#define CAP     256
#define A_TOT   (T_TOK * TOPK)
#define SCALE_F 2.5f
#define GUP_COLS (2 * I_DIM)
#define SH_ACT   1024
#define SH_GUP   2048

#define KC 32
#define SA 40
#define SB 72

// ------------------------------- scratch -----------------------------------
__device__ float g_w[A_TOT];
__device__ int   g_eidx[A_TOT];
__device__ int   g_counts[E_EXP];
__device__ int   g_list[E_EXP * CAP];
__device__ int   g_keep[A_TOT];

__device__ __nv_bfloat16 g_xs_h[T_TOK * H_DIM];
__device__ __nv_bfloat16 g_xs_l[T_TOK * H_DIM];
__device__ __nv_bfloat16 g_wsgu_h[H_DIM * SH_GUP];
__device__ __nv_bfloat16 g_wsgu_l[H_DIM * SH_GUP];
__device__ __nv_bfloat16 g_wsd_h[SH_ACT * H_DIM];
__device__ __nv_bfloat16 g_wsd_l[SH_ACT * H_DIM];
__device__ __nv_bfloat16 g_wgu_h[(size_t)E_EXP * H_DIM * GUP_COLS];
__device__ __nv_bfloat16 g_wgu_l[(size_t)E_EXP * H_DIM * GUP_COLS];
__device__ __nv_bfloat16 g_wd_h[(size_t)E_EXP * I_DIM * H_DIM];
__device__ __nv_bfloat16 g_wd_l[(size_t)E_EXP * I_DIM * H_DIM];
__device__ __nv_bfloat16 g_acts_h[T_TOK * SH_ACT];
__device__ __nv_bfloat16 g_acts_l[T_TOK * SH_ACT];
__device__ __nv_bfloat16 g_actr_h[(size_t)E_EXP * CAP * I_DIM];
__device__ __nv_bfloat16 g_actr_l[(size_t)E_EXP * CAP * I_DIM];
__device__ float g_ybuf[(size_t)A_TOT * H_DIM];

// ------------------------------- helpers -----------------------------------
__device__ __forceinline__ unsigned pack2(__nv_bfloat16 a, __nv_bfloat16 b) {
    __nv_bfloat162 t = __halves2bfloat162(a, b);
    return *(unsigned*)&t;
}

__device__ __forceinline__ void f2hl2(float x, float y, unsigned& h, unsigned& l) {
    __nv_bfloat16 h0 = __float2bfloat16(x), h1 = __float2bfloat16(y);
    __nv_bfloat16 l0 = __float2bfloat16(x - __bfloat162float(h0));
    __nv_bfloat16 l1 = __float2bfloat16(y - __bfloat162float(h1));
    h = pack2(h0, h1);
    l = pack2(l0, l1);
}

__device__ __forceinline__ void mma_bf16(float c[4],
    unsigned a0, unsigned a1, unsigned a2, unsigned a3,
    unsigned b0, unsigned b1)
{
    asm volatile(
        "mma.sync.aligned.m16n8k16.row.col.f32.bf16.bf16.f32 "
        "{%0,%1,%2,%3}, {%4,%5,%6,%7}, {%8,%9}, {%0,%1,%2,%3};"
        : "+f"(c[0]), "+f"(c[1]), "+f"(c[2]), "+f"(c[3])
        : "r"(a0), "r"(a1), "r"(a2), "r"(a3), "r"(b0), "r"(b1));
}

__device__ __forceinline__ void ldsm4(unsigned* r, uint32_t addr) {
    asm volatile("ldmatrix.sync.aligned.m8n8.x4.shared.b16 {%0,%1,%2,%3}, [%4];"
        : "=r"(r[0]), "=r"(r[1]), "=r"(r[2]), "=r"(r[3]) : "r"(addr));
}
__device__ __forceinline__ void ldsm4t(unsigned* r, uint32_t addr) {
    asm volatile("ldmatrix.sync.aligned.m8n8.x4.trans.shared.b16 {%0,%1,%2,%3}, [%4];"
        : "=r"(r[0]), "=r"(r[1]), "=r"(r[2]), "=r"(r[3]) : "r"(addr));
}

// ------------------------------- split -------------------------------------
__global__ __launch_bounds__(256) void split_kernel(
    const float4* __restrict__ src, uint2* __restrict__ hi, uint2* __restrict__ lo, int n4)
{
    int i = blockIdx.x * 256 + threadIdx.x;
    if (i >= n4) return;
    float4 v = src[i];
    unsigned h01, l01, h23, l23;
    f2hl2(v.x, v.y, h01, l01);
    f2hl2(v.z, v.w, h23, l23);
    hi[i] = make_uint2(h01, h23);
    lo[i] = make_uint2(l01, l23);
}

// ------------------------ router (warp per token) --------------------------
__global__ __launch_bounds__(256) void router_kernel(
    const float* __restrict__ x, const float* __restrict__ gw,
    const float* __restrict__ bias)
{
    __shared__ float xs[8][H_DIM];
    const int tid = threadIdx.x;
    const int warp = tid >> 5, lane = tid & 31;
    const unsigned FULL = 0xffffffffu;

    // cooperative load of 8 token rows
    for (int i = tid; i < 8 * (H_DIM / 4); i += 256) {
        int row = i >> 8, c4 = (i & 255) * 4;
        *(float4*)&xs[row][c4] = *(const float4*)(x + (size_t)(blockIdx.x * 8 + row) * H_DIM + c4);
    }
    __syncthreads();

    const int t = blockIdx.x * 8 + warp;

    // logits: lane handles experts (lane) and (lane+32)
    float acc0 = 0.f, acc1 = 0.f;
#pragma unroll 8
    for (int h = 0; h < H_DIM; h++) {
        float xv = xs[warp][h];
        acc0 += xv * gw[h * E_EXP + lane];
        acc1 += xv * gw[h * E_EXP + lane + 32];
    }
    float sc0 = 1.f / (1.f + expf(-acc0));
    float sc1 = 1.f / (1.f + expf(-acc1));
    float s0 = sc0 + bias[lane];
    float s1 = sc1 + bias[lane + 32];

    // per-group (8 experts) top-2 sum via xor-shuffle merges within 8-lane segs
    float m1a = s0, m2a = -INFINITY;
    float m1b = s1, m2b = -INFINITY;
#pragma unroll
    for (int off = 4; off >= 1; off >>= 1) {
        float o1 = __shfl_xor_sync(FULL, m1a, off);
        float o2 = __shfl_xor_sync(FULL, m2a, off);
        if (o1 > m1a) { m2a = fmaxf(m1a, o2); m1a = o1; }
        else          { m2a = fmaxf(m2a, o1); }
        o1 = __shfl_xor_sync(FULL, m1b, off);
        o2 = __shfl_xor_sync(FULL, m2b, off);
        if (o1 > m1b) { m2b = fmaxf(m1b, o2); m1b = o1; }
        else          { m2b = fmaxf(m2b, o1); }
    }
    float gsv0 = m1a + m2a;   // group (lane>>3)      in [0,4)
    float gsv1 = m1b + m2b;   // group (lane>>3) + 4  in [4,8)

    // gather all 8 group scores into every lane
    float gs[NGROUP];
#pragma unroll
    for (int g = 0; g < 4; g++) {
        gs[g]     = __shfl_sync(FULL, gsv0, g * 8);
        gs[4 + g] = __shfl_sync(FULL, gsv1, g * 8);
    }
    // top-3 groups (strict > : lowest index wins ties), redundant per-lane
    bool gsel[NGROUP];
#pragma unroll
    for (int g = 0; g < NGROUP; g++) gsel[g] = false;
#pragma unroll
    for (int it = 0; it < TKG; it++) {
        int bi = -1; float bv = -INFINITY;
#pragma unroll
        for (int g = 0; g < NGROUP; g++)
            if (!gsel[g] && gs[g] > bv) { bv = gs[g]; bi = g; }
        gsel[bi] = true;
    }

    // mask experts in unselected groups
    float t0 = gsel[lane >> 3]       ? s0 : -INFINITY;
    float t1 = gsel[(lane >> 3) + 4] ? s1 : -INFINITY;

    // top-6 experts via warp argmax (ties -> lower expert index)
    int   idxk[TOPK];
    float wvk[TOPK];
    float wsum = 0.f;
#pragma unroll
    for (int k = 0; k < TOPK; k++) {
        float bv; int be;
        if (t0 >= t1) { bv = t0; be = lane; }
        else          { bv = t1; be = lane + 32; }
#pragma unroll
        for (int off = 16; off >= 1; off >>= 1) {
            float ov = __shfl_xor_sync(FULL, bv, off);
            int   oi = __shfl_xor_sync(FULL, be, off);
            if (ov > bv || (ov == bv && oi < be)) { bv = ov; be = oi; }
        }
        float scw = __shfl_sync(FULL, (be & 32) ? sc1 : sc0, be & 31);
        idxk[k] = be;
        wvk[k]  = scw;
        wsum   += scw;
        if (lane == (be & 31)) {
            if (be & 32) t1 = -INFINITY; else t0 = -INFINITY;
        }
    }
    if (lane == 0) {
        float inv = 1.f / wsum;
#pragma unroll
        for (int k = 0; k < TOPK; k++) {
            g_w[t * TOPK + k]    = wvk[k] * inv;
            g_eidx[t * TOPK + k] = idxk[k];
        }
    }
}

// ------------------------------ dispatch -----------------------------------
__global__ __launch_bounds__(256) void dispatch_kernel()
{
    const int e = blockIdx.x, tid = threadIdx.x;
    const int lane = tid & 31, wid = tid >> 5;
    __shared__ int warp_tot[8];
    int base = 0;
    for (int chunk = 0; chunk < A_TOT; chunk += 256) {
        int a = chunk + tid;
        int m = (a < A_TOT && g_eidx[a] == e) ? 1 : 0;
        unsigned bal = __ballot_sync(0xffffffffu, m);
        if (lane == 0) warp_tot[wid] = __popc(bal);
        __syncthreads();
        int woff = 0, tot = 0;
#pragma unroll
        for (int i = 0; i < 8; i++) { if (i < wid) woff += warp_tot[i]; tot += warp_tot[i]; }
        if (m) {
            int pos = base + woff + __popc(bal & ((1u << lane) - 1u));
            if (pos < CAP) g_list[e * CAP + pos] = a;
            g_keep[a] = (pos < CAP) ? 1 : 0;
        }
        base += tot;
        __syncthreads();
    }
    if (tid == 0) g_counts[e] = base < CAP ? base : CAP;
}

// ===========================================================================
// GEMM kernels: 64x64 tile, 256 thr = 8 warps (4M x 2N), warp = 16x32.
// ===========================================================================

__global__ __launch_bounds__(256) void shared_gateup_tc()
{
    __shared__ __align__(16) __nv_bfloat16 sAh[64 * SA], sAl[64 * SA];
    __shared__ __align__(16) __nv_bfloat16 sGh[KC * SB], sGl[KC * SB];
    __shared__ __align__(16) __nv_bfloat16 sUh[KC * SB], sUl[KC * SB];

    const int tid = threadIdx.x, lane = tid & 31, wid = tid >> 5;
    const int gid = lane >> 2, tig = lane & 3;
    const int wm = wid & 3, wn = wid >> 2;
    const int rb = blockIdx.y * 64, cb = blockIdx.x * 64;

    const int ar = tid >> 2, ac8 = (tid & 3) * 8;
    const int bk = tid >> 3, bn8 = (tid & 7) * 8;

    const __nv_bfloat16* aH = g_xs_h + (size_t)(rb + ar) * H_DIM + ac8;
    const __nv_bfloat16* aL = g_xs_l + (size_t)(rb + ar) * H_DIM + ac8;
    const __nv_bfloat16* gH = g_wsgu_h + (size_t)bk * SH_GUP + cb + bn8;
    const __nv_bfloat16* gL = g_wsgu_l + (size_t)bk * SH_GUP + cb + bn8;
    const __nv_bfloat16* uH = gH + SH_ACT;
    const __nv_bfloat16* uL = gL + SH_ACT;

    const uint32_t aBase = (uint32_t)((((wm * 16 + (lane & 15)) * SA) + (lane >> 4) * 8) * 2);
    uint32_t aOffH = (uint32_t)__cvta_generic_to_shared(sAh) + aBase;
    uint32_t aOffL = (uint32_t)__cvta_generic_to_shared(sAl) + aBase;
    const int mB = lane >> 3;
    const uint32_t bBase = (uint32_t)(((((mB & 1) * 8 + (lane & 7)) * SB) + wn * 32 + (mB >> 1) * 8) * 2);
    uint32_t gOffH = (uint32_t)__cvta_generic_to_shared(sGh) + bBase;
    uint32_t gOffL = (uint32_t)__cvta_generic_to_shared(sGl) + bBase;
    uint32_t uOffH = (uint32_t)__cvta_generic_to_shared(sUh) + bBase;
    uint32_t uOffL = (uint32_t)__cvta_generic_to_shared(sUl) + bBase;

    float accG[4][4] = {}, accU[4][4] = {};

    for (int k0 = 0; k0 < H_DIM; k0 += KC) {
        *(uint4*)&sAh[ar * SA + ac8] = *(const uint4*)(aH + k0);
        *(uint4*)&sAl[ar * SA + ac8] = *(const uint4*)(aL + k0);
        *(uint4*)&sGh[bk * SB + bn8] = *(const uint4*)(gH + (size_t)k0 * SH_GUP);
        *(uint4*)&sGl[bk * SB + bn8] = *(const uint4*)(gL + (size_t)k0 * SH_GUP);
        *(uint4*)&sUh[bk * SB + bn8] = *(const uint4*)(uH + (size_t)k0 * SH_GUP);
        *(uint4*)&sUl[bk * SB + bn8] = *(const uint4*)(uL + (size_t)k0 * SH_GUP);
        __syncthreads();
#pragma unroll
        for (int s = 0; s < 2; s++) {
            unsigned ah[4], al[4];
            ldsm4(ah, aOffH + s * 32);
            ldsm4(al, aOffL + s * 32);
            unsigned gh[8], gl[8], uh[8], ul[8];
#pragma unroll
            for (int g = 0; g < 2; g++) {
                uint32_t off = (uint32_t)(s * 16 * SB) * 2 + g * 32;
                ldsm4t(&gh[g * 4], gOffH + off);
                ldsm4t(&gl[g * 4], gOffL + off);
                ldsm4t(&uh[g * 4], uOffH + off);
                ldsm4t(&ul[g * 4], uOffL + off);
            }
#pragma unroll
            for (int t = 0; t < 4; t++) {
                int p = (t >> 1) * 4 + (t & 1) * 2;
                mma_bf16(accG[t], ah[0], ah[1], ah[2], ah[3], gh[p], gh[p + 1]);
                mma_bf16(accG[t], ah[0], ah[1], ah[2], ah[3], gl[p], gl[p + 1]);
                mma_bf16(accG[t], al[0], al[1], al[2], al[3], gh[p], gh[p + 1]);
                mma_bf16(accU[t], ah[0], ah[1], ah[2], ah[3], uh[p], uh[p + 1]);
                mma_bf16(accU[t], ah[0], ah[1], ah[2], ah[3], ul[p], ul[p + 1]);
                mma_bf16(accU[t], al[0], al[1], al[2], al[3], uh[p], uh[p + 1]);
            }
        }
        __syncthreads();
    }
    const int r0 = rb + wm * 16 + gid;
#pragma unroll
    for (int t = 0; t < 4; t++) {
        int c = cb + wn * 32 + t * 8 + tig * 2;
#pragma unroll
        for (int i = 0; i < 2; i++) {
            int r = r0 + i * 8;
            float g0 = accG[t][i * 2], u0 = accU[t][i * 2];
            float g1 = accG[t][i * 2 + 1], u1 = accU[t][i * 2 + 1];
            float a0 = (g0 / (1.f + expf(-g0))) * u0;
            float a1 = (g1 / (1.f + expf(-g1))) * u1;
            unsigned h, l;
            f2hl2(a0, a1, h, l);
            *(unsigned*)&g_acts_h[(size_t)r * SH_ACT + c] = h;
            *(unsigned*)&g_acts_l[(size_t)r * SH_ACT + c] = l;
        }
    }
}

__global__ __launch_bounds__(256) void shared_down_tc(float* __restrict__ out)
{
    __shared__ __align__(16) __nv_bfloat16 sAh[64 * SA], sAl[64 * SA];
    __shared__ __align__(16) __nv_bfloat16 sBh[KC * SB], sBl[KC * SB];

    const int tid = threadIdx.x, lane = tid & 31, wid = tid >> 5;
    const int gid = lane >> 2, tig = lane & 3;
    const int wm = wid & 3, wn = wid >> 2;
    const int rb = blockIdx.y * 64, cb = blockIdx.x * 64;

    const int ar = tid >> 2, ac8 = (tid & 3) * 8;
    const int bk = tid >> 3, bn8 = (tid & 7) * 8;

    const __nv_bfloat16* aH = g_acts_h + (size_t)(rb + ar) * SH_ACT + ac8;
    const __nv_bfloat16* aL = g_acts_l + (size_t)(rb + ar) * SH_ACT + ac8;
    const __nv_bfloat16* bH = g_wsd_h + (size_t)bk * H_DIM + cb + bn8;
    const __nv_bfloat16* bL = g_wsd_l + (size_t)bk * H_DIM + cb + bn8;

    const uint32_t aBase = (uint32_t)((((wm * 16 + (lane & 15)) * SA) + (lane >> 4) * 8) * 2);
    uint32_t aOffH = (uint32_t)__cvta_generic_to_shared(sAh) + aBase;
    uint32_t aOffL = (uint32_t)__cvta_generic_to_shared(sAl) + aBase;
    const int mB = lane >> 3;
    const uint32_t bBase = (uint32_t)(((((mB & 1) * 8 + (lane & 7)) * SB) + wn * 32 + (mB >> 1) * 8) * 2);
    uint32_t bOffH = (uint32_t)__cvta_generic_to_shared(sBh) + bBase;
    uint32_t bOffL = (uint32_t)__cvta_generic_to_shared(sBl) + bBase;

    float acc[4][4] = {};

    for (int k0 = 0; k0 < SH_ACT; k0 += KC) {
        *(uint4*)&sAh[ar * SA + ac8] = *(const uint4*)(aH + k0);
        *(uint4*)&sAl[ar * SA + ac8] = *(const uint4*)(aL + k0);
        *(uint4*)&sBh[bk * SB + bn8] = *(const uint4*)(bH + (size_t)k0 * H_DIM);
        *(uint4*)&sBl[bk * SB + bn8] = *(const uint4*)(bL + (size_t)k0 * H_DIM);
        __syncthreads();
#pragma unroll
        for (int s = 0; s < 2; s++) {
            unsigned ah[4], al[4];
            ldsm4(ah, aOffH + s * 32);
            ldsm4(al, aOffL + s * 32);
            unsigned bh[8], bl[8];
#pragma unroll
            for (int g = 0; g < 2; g++) {
                uint32_t off = (uint32_t)(s * 16 * SB) * 2 + g * 32;
                ldsm4t(&bh[g * 4], bOffH + off);
                ldsm4t(&bl[g * 4], bOffL + off);
            }
#pragma unroll
            for (int t = 0; t < 4; t++) {
                int p = (t >> 1) * 4 + (t & 1) * 2;
                mma_bf16(acc[t], ah[0], ah[1], ah[2], ah[3], bh[p], bh[p + 1]);
                mma_bf16(acc[t], ah[0], ah[1], ah[2], ah[3], bl[p], bl[p + 1]);
                mma_bf16(acc[t], al[0], al[1], al[2], al[3], bh[p], bh[p + 1]);
            }
        }
        __syncthreads();
    }
    const int r0 = rb + wm * 16 + gid;
#pragma unroll
    for (int t = 0; t < 4; t++) {
        int c = cb + wn * 32 + t * 8 + tig * 2;
        out[(size_t)(r0    ) * H_DIM + c + 0] = acc[t][0];
        out[(size_t)(r0    ) * H_DIM + c + 1] = acc[t][1];
        out[(size_t)(r0 + 8) * H_DIM + c + 0] = acc[t][2];
        out[(size_t)(r0 + 8) * H_DIM + c + 1] = acc[t][3];
    }
}

__global__ __launch_bounds__(256) void routed_gateup_tc()
{
    const int e = blockIdx.z;
    const int cnt = g_counts[e];
    const int r0b = blockIdx.y * 64;
    if (r0b >= cnt) return;

    __shared__ __align__(16) __nv_bfloat16 sAh[64 * SA], sAl[64 * SA];
    __shared__ __align__(16) __nv_bfloat16 sGh[KC * SB], sGl[KC * SB];
    __shared__ __align__(16) __nv_bfloat16 sUh[KC * SB], sUl[KC * SB];

    const int tid = threadIdx.x, lane = tid & 31, wid = tid >> 5;
    const int gid = lane >> 2, tig = lane & 3;
    const int wm = wid & 3, wn = wid >> 2;
    const int cb = blockIdx.x * 64;

    const int ar = tid >> 2, ac8 = (tid & 3) * 8;
    const int bk = tid >> 3, bn8 = (tid & 7) * 8;

    int tok = 0;
    {
        int r = r0b + ar;
        if (r < cnt) tok = g_list[e * CAP + r] / TOPK;
    }
    const __nv_bfloat16* aH = g_xs_h + (size_t)tok * H_DIM + ac8;
    const __nv_bfloat16* aL = g_xs_l + (size_t)tok * H_DIM + ac8;
    const __nv_bfloat16* gH = g_wgu_h + (size_t)e * H_DIM * GUP_COLS + (size_t)bk * GUP_COLS + cb + bn8;
    const __nv_bfloat16* gL = g_wgu_l + (size_t)e * H_DIM * GUP_COLS + (size_t)bk * GUP_COLS + cb + bn8;
    const __nv_bfloat16* uH = gH + I_DIM;
    const __nv_bfloat16* uL = gL + I_DIM;

    const uint32_t aBase = (uint32_t)((((wm * 16 + (lane & 15)) * SA) + (lane >> 4) * 8) * 2);
    uint32_t aOffH = (uint32_t)__cvta_generic_to_shared(sAh) + aBase;
    uint32_t aOffL = (uint32_t)__cvta_generic_to_shared(sAl) + aBase;
    const int mB = lane >> 3;
    const uint32_t bBase = (uint32_t)(((((mB & 1) * 8 + (lane & 7)) * SB) + wn * 32 + (mB >> 1) * 8) * 2);
    uint32_t gOffH = (uint32_t)__cvta_generic_to_shared(sGh) + bBase;
    uint32_t gOffL = (uint32_t)__cvta_generic_to_shared(sGl) + bBase;
    uint32_t uOffH = (uint32_t)__cvta_generic_to_shared(sUh) + bBase;
    uint32_t uOffL = (uint32_t)__cvta_generic_to_shared(sUl) + bBase;

    float accG[4][4] = {}, accU[4][4] = {};

    for (int k0 = 0; k0 < H_DIM; k0 += KC) {
        *(uint4*)&sAh[ar * SA + ac8] = *(const uint4*)(aH + k0);
        *(uint4*)&sAl[ar * SA + ac8] = *(const uint4*)(aL + k0);
        *(uint4*)&sGh[bk * SB + bn8] = *(const uint4*)(gH + (size_t)k0 * GUP_COLS);
        *(uint4*)&sGl[bk * SB + bn8] = *(const uint4*)(gL + (size_t)k0 * GUP_COLS);
        *(uint4*)&sUh[bk * SB + bn8] = *(const uint4*)(uH + (size_t)k0 * GUP_COLS);
        *(uint4*)&sUl[bk * SB + bn8] = *(const uint4*)(uL + (size_t)k0 * GUP_COLS);
        __syncthreads();
#pragma unroll
        for (int s = 0; s < 2; s++) {
            unsigned ah[4], al[4];
            ldsm4(ah, aOffH + s * 32);
            ldsm4(al, aOffL + s * 32);
            unsigned gh[8], gl[8], uh[8], ul[8];
#pragma unroll
            for (int g = 0; g < 2; g++) {
                uint32_t off = (uint32_t)(s * 16 * SB) * 2 + g * 32;
                ldsm4t(&gh[g * 4], gOffH + off);
                ldsm4t(&gl[g * 4], gOffL + off);
                ldsm4t(&uh[g * 4], uOffH + off);
                ldsm4t(&ul[g * 4], uOffL + off);
            }
#pragma unroll
            for (int t = 0; t < 4; t++) {
                int p = (t >> 1) * 4 + (t & 1) * 2;
                mma_bf16(accG[t], ah[0], ah[1], ah[2], ah[3], gh[p], gh[p + 1]);
                mma_bf16(accG[t], ah[0], ah[1], ah[2], ah[3], gl[p], gl[p + 1]);
                mma_bf16(accG[t], al[0], al[1], al[2], al[3], gh[p], gh[p + 1]);
                mma_bf16(accU[t], ah[0], ah[1], ah[2], ah[3], uh[p], uh[p + 1]);
                mma_bf16(accU[t], ah[0], ah[1], ah[2], ah[3], ul[p], ul[p + 1]);
                mma_bf16(accU[t], al[0], al[1], al[2], al[3], uh[p], uh[p + 1]);
            }
        }
        __syncthreads();
    }
    const int rw = wm * 16 + gid;
#pragma unroll
    for (int t = 0; t < 4; t++) {
        int c = cb + wn * 32 + t * 8 + tig * 2;
#pragma unroll
        for (int i = 0; i < 2; i++) {
            int r = r0b + rw + i * 8;
            if (r < cnt) {
                float g0 = accG[t][i * 2], u0 = accU[t][i * 2];
                float g1 = accG[t][i * 2 + 1], u1 = accU[t][i * 2 + 1];
                float a0 = (g0 / (1.f + expf(-g0))) * u0;
                float a1 = (g1 / (1.f + expf(-g1))) * u1;
                unsigned h, l;
                f2hl2(a0, a1, h, l);
                *(unsigned*)&g_actr_h[((size_t)e * CAP + r) * I_DIM + c] = h;
                *(unsigned*)&g_actr_l[((size_t)e * CAP + r) * I_DIM + c] = l;
            }
        }
    }
}

__global__ __launch_bounds__(256) void routed_down_tc()
{
    const int e = blockIdx.z;
    const int cnt = g_counts[e];
    const int r0b = blockIdx.y * 64;
    if (r0b >= cnt) return;

    __shared__ __align__(16) __nv_bfloat16 sAh[64 * SA], sAl[64 * SA];
    __shared__ __align__(16) __nv_bfloat16 sBh[KC * SB], sBl[KC * SB];

    const int tid = threadIdx.x, lane = tid & 31, wid = tid >> 5;
    const int gid = lane >> 2, tig = lane & 3;
    const int wm = wid & 3, wn = wid >> 2;
    const int cb = blockIdx.x * 64;

    const int ar = tid >> 2, ac8 = (tid & 3) * 8;
    const int bk = tid >> 3, bn8 = (tid & 7) * 8;

    const __nv_bfloat16* aH = g_actr_h + ((size_t)e * CAP + (r0b + ar)) * I_DIM + ac8;
    const __nv_bfloat16* aL = g_actr_l + ((size_t)e * CAP + (r0b + ar)) * I_DIM + ac8;
    const __nv_bfloat16* bH = g_wd_h + (size_t)e * I_DIM * H_DIM + (size_t)bk * H_DIM + cb + bn8;
    const __nv_bfloat16* bL = g_wd_l + (size_t)e * I_DIM * H_DIM + (size_t)bk * H_DIM + cb + bn8;

    const uint32_t aBase = (uint32_t)((((wm * 16 + (lane & 15)) * SA) + (lane >> 4) * 8) * 2);
    uint32_t aOffH = (uint32_t)__cvta_generic_to_shared(sAh) + aBase;
    uint32_t aOffL = (uint32_t)__cvta_generic_to_shared(sAl) + aBase;
    const int mB = lane >> 3;
    const uint32_t bBase = (uint32_t)(((((mB & 1) * 8 + (lane & 7)) * SB) + wn * 32 + (mB >> 1) * 8) * 2);
    uint32_t bOffH = (uint32_t)__cvta_generic_to_shared(sBh) + bBase;
    uint32_t bOffL = (uint32_t)__cvta_generic_to_shared(sBl) + bBase;

    float acc[4][4] = {};

    for (int k0 = 0; k0 < I_DIM; k0 += KC) {
        *(uint4*)&sAh[ar * SA + ac8] = *(const uint4*)(aH + k0);
        *(uint4*)&sAl[ar * SA + ac8] = *(const uint4*)(aL + k0);
        *(uint4*)&sBh[bk * SB + bn8] = *(const uint4*)(bH + (size_t)k0 * H_DIM);
        *(uint4*)&sBl[bk * SB + bn8] = *(const uint4*)(bL + (size_t)k0 * H_DIM);
        __syncthreads();
#pragma unroll
        for (int s = 0; s < 2; s++) {
            unsigned ah[4], al[4];
            ldsm4(ah, aOffH + s * 32);
            ldsm4(al, aOffL + s * 32);
            unsigned bh[8], bl[8];
#pragma unroll
            for (int g = 0; g < 2; g++) {
                uint32_t off = (uint32_t)(s * 16 * SB) * 2 + g * 32;
                ldsm4t(&bh[g * 4], bOffH + off);
                ldsm4t(&bl[g * 4], bOffL + off);
            }
#pragma unroll
            for (int t = 0; t < 4; t++) {
                int p = (t >> 1) * 4 + (t & 1) * 2;
                mma_bf16(acc[t], ah[0], ah[1], ah[2], ah[3], bh[p], bh[p + 1]);
                mma_bf16(acc[t], ah[0], ah[1], ah[2], ah[3], bl[p], bl[p + 1]);
                mma_bf16(acc[t], al[0], al[1], al[2], al[3], bh[p], bh[p + 1]);
            }
        }
        __syncthreads();
    }
    const int rw = wm * 16 + gid;
#pragma unroll
    for (int t = 0; t < 4; t++) {
        int c = cb + wn * 32 + t * 8 + tig * 2;
#pragma unroll
        for (int i = 0; i < 2; i++) {
            int r = r0b + rw + i * 8;
            if (r < cnt) {
                int a = g_list[e * CAP + r];
                g_ybuf[(size_t)a * H_DIM + c + 0] = acc[t][i * 2 + 0];
                g_ybuf[(size_t)a * H_DIM + c + 1] = acc[t][i * 2 + 1];
            }
        }
    }
}

// ------------------------------- combine -----------------------------------
__global__ __launch_bounds__(256) void combine_kernel(float* __restrict__ out)
{
    const int t = blockIdx.x;
    const int h4 = threadIdx.x * 4;
    float4 o = *(float4*)(out + (size_t)t * H_DIM + h4);
    float r0 = o.x, r1 = o.y, r2 = o.z, r3 = o.w;
#pragma unroll
    for (int k = 0; k < TOPK; k++) {
        int a = t * TOPK + k;
        if (g_keep[a]) {
            float wv = g_w[a] * SCALE_F;
            float4 y = *(const float4*)(g_ybuf + (size_t)a * H_DIM + h4);
            r0 += wv * y.x; r1 += wv * y.y; r2 += wv * y.z; r3 += wv * y.w;
        }
    }
    *(float4*)(out + (size_t)t * H_DIM + h4) = make_float4(r0, r1, r2, r3);
}

// ------------------------------- launcher ----------------------------------
extern "C" void kernel_launch(void* const* d_in, const int* in_sizes, int n_in,
                              void* d_out, int out_size)
{
    const float* x          = (const float*)d_in[0];
    const float* gate_w     = (const float*)d_in[1];
    const float* e_bias     = (const float*)d_in[2];
    const float* w_gate_up  = (const float*)d_in[3];
    const float* w_down     = (const float*)d_in[4];
    const float* ws_gate_up = (const float*)d_in[5];
    const float* ws_down    = (const float*)d_in[6];
    float* out = (float*)d_out;

    __nv_bfloat16 *xs_h, *xs_l, *wsgu_h, *wsgu_l, *wsd_h, *wsd_l;
    __nv_bfloat16 *wgu_h, *wgu_l, *wd_h, *wd_l;
    cudaGetSymbolAddress((void**)&xs_h, g_xs_h);
    cudaGetSymbolAddress((void**)&xs_l, g_xs_l);
    cudaGetSymbolAddress((void**)&wsgu_h, g_wsgu_h);
    cudaGetSymbolAddress((void**)&wsgu_l, g_wsgu_l);
    cudaGetSymbolAddress((void**)&wsd_h, g_wsd_h);
    cudaGetSymbolAddress((void**)&wsd_l, g_wsd_l);
    cudaGetSymbolAddress((void**)&wgu_h, g_wgu_h);
    cudaGetSymbolAddress((void**)&wgu_l, g_wgu_l);
    cudaGetSymbolAddress((void**)&wd_h, g_wd_h);
    cudaGetSymbolAddress((void**)&wd_l, g_wd_l);

    auto split = [](const float* s, __nv_bfloat16* h, __nv_bfloat16* l, size_t n) {
        int n4 = (int)(n / 4);
        split_kernel<<<(n4 + 255) / 256, 256>>>((const float4*)s, (uint2*)h, (uint2*)l, n4);
    };

    split(x,          xs_h,   xs_l,   (size_t)T_TOK * H_DIM);
    split(ws_gate_up, wsgu_h, wsgu_l, (size_t)H_DIM * SH_GUP);
    split(ws_down,    wsd_h,  wsd_l,  (size_t)SH_ACT * H_DIM);
    split(w_gate_up,  wgu_h,  wgu_l,  (size_t)E_EXP * H_DIM * GUP_COLS);
    split(w_down,     wd_h,   wd_l,   (size_t)E_EXP * I_DIM * H_DIM);

    router_kernel<<<T_TOK / 8, 256>>>(x, gate_w, e_bias);
    dispatch_kernel<<<E_EXP, 256>>>();

    shared_gateup_tc<<<dim3(SH_ACT / 64, T_TOK / 64), 256>>>();
    shared_down_tc<<<dim3(H_DIM / 64, T_TOK / 64), 256>>>(out);
    routed_gateup_tc<<<dim3(I_DIM / 64, CAP / 64, E_EXP), 256>>>();
    routed_down_tc<<<dim3(H_DIM / 64, CAP / 64, E_EXP), 256>>>();
    combine_kernel<<<T_TOK, 256>>>(out);
}

// round 8
// speedup vs baseline: 1.7093x; 1.1339x over previous
#include <cuda_runtime.h>
#include <cuda_bf16.h>
#include <cstdint>
#include <math.h>

// ---------------------------------------------------------------------------
// DeepseekV2 MoE. Round-7 pipeline, but routed GEMMs read fp32 expert weights
// directly and convert to hi/lo bf16 inline in the B smem producer
// (structure otherwise identical: 256 thr, 64x64 tiles, grid.y = CAP/64).
// ---------------------------------------------------------------------------

#define T_TOK   1024
#define H_DIM   1024
#define E_EXP   64
#define I_DIM   512
#define TOPK    6
#define NGROUP  8
#define TKG     3
#define CAP     256
#define A_TOT   (T_TOK * TOPK)
#define SCALE_F 2.5f
#define GUP_COLS (2 * I_DIM)
#define SH_ACT   1024
#define SH_GUP   2048

#define KC 32
#define SA 40
#define SB 72

// ------------------------------- scratch -----------------------------------
__device__ float g_w[A_TOT];
__device__ int   g_eidx[A_TOT];
__device__ int   g_counts[E_EXP];
__device__ int   g_list[E_EXP * CAP];
__device__ int   g_keep[A_TOT];

__device__ __nv_bfloat16 g_xs_h[T_TOK * H_DIM];
__device__ __nv_bfloat16 g_xs_l[T_TOK * H_DIM];
__device__ __nv_bfloat16 g_wsgu_h[H_DIM * SH_GUP];
__device__ __nv_bfloat16 g_wsgu_l[H_DIM * SH_GUP];
__device__ __nv_bfloat16 g_wsd_h[SH_ACT * H_DIM];
__device__ __nv_bfloat16 g_wsd_l[SH_ACT * H_DIM];
__device__ __nv_bfloat16 g_acts_h[T_TOK * SH_ACT];
__device__ __nv_bfloat16 g_acts_l[T_TOK * SH_ACT];
__device__ __nv_bfloat16 g_actr_h[(size_t)E_EXP * CAP * I_DIM];
__device__ __nv_bfloat16 g_actr_l[(size_t)E_EXP * CAP * I_DIM];
__device__ float g_ybuf[(size_t)A_TOT * H_DIM];

// ------------------------------- helpers -----------------------------------
__device__ __forceinline__ unsigned pack2(__nv_bfloat16 a, __nv_bfloat16 b) {
    __nv_bfloat162 t = __halves2bfloat162(a, b);
    return *(unsigned*)&t;
}

__device__ __forceinline__ void f2hl2(float x, float y, unsigned& h, unsigned& l) {
    __nv_bfloat16 h0 = __float2bfloat16(x), h1 = __float2bfloat16(y);
    __nv_bfloat16 l0 = __float2bfloat16(x - __bfloat162float(h0));
    __nv_bfloat16 l1 = __float2bfloat16(y - __bfloat162float(h1));
    h = pack2(h0, h1);
    l = pack2(l0, l1);
}

__device__ __forceinline__ void mma_bf16(float c[4],
    unsigned a0, unsigned a1, unsigned a2, unsigned a3,
    unsigned b0, unsigned b1)
{
    asm volatile(
        "mma.sync.aligned.m16n8k16.row.col.f32.bf16.bf16.f32 "
        "{%0,%1,%2,%3}, {%4,%5,%6,%7}, {%8,%9}, {%0,%1,%2,%3};"
        : "+f"(c[0]), "+f"(c[1]), "+f"(c[2]), "+f"(c[3])
        : "r"(a0), "r"(a1), "r"(a2), "r"(a3), "r"(b0), "r"(b1));
}

__device__ __forceinline__ void ldsm4(unsigned* r, uint32_t addr) {
    asm volatile("ldmatrix.sync.aligned.m8n8.x4.shared.b16 {%0,%1,%2,%3}, [%4];"
        : "=r"(r[0]), "=r"(r[1]), "=r"(r[2]), "=r"(r[3]) : "r"(addr));
}
__device__ __forceinline__ void ldsm4t(unsigned* r, uint32_t addr) {
    asm volatile("ldmatrix.sync.aligned.m8n8.x4.trans.shared.b16 {%0,%1,%2,%3}, [%4];"
        : "=r"(r[0]), "=r"(r[1]), "=r"(r[2]), "=r"(r[3]) : "r"(addr));
}

// ------------------------------- split -------------------------------------
__global__ __launch_bounds__(256) void split_kernel(
    const float4* __restrict__ src, uint2* __restrict__ hi, uint2* __restrict__ lo, int n4)
{
    int i = blockIdx.x * 256 + threadIdx.x;
    if (i >= n4) return;
    float4 v = src[i];
    unsigned h01, l01, h23, l23;
    f2hl2(v.x, v.y, h01, l01);
    f2hl2(v.z, v.w, h23, l23);
    hi[i] = make_uint2(h01, h23);
    lo[i] = make_uint2(l01, l23);
}

// ------------------------ router (warp per token) --------------------------
__global__ __launch_bounds__(256) void router_kernel(
    const float* __restrict__ x, const float* __restrict__ gw,
    const float* __restrict__ bias)
{
    __shared__ float xs[8][H_DIM];
    const int tid = threadIdx.x;
    const int warp = tid >> 5, lane = tid & 31;
    const unsigned FULL = 0xffffffffu;

    for (int i = tid; i < 8 * (H_DIM / 4); i += 256) {
        int row = i >> 8, c4 = (i & 255) * 4;
        *(float4*)&xs[row][c4] = *(const float4*)(x + (size_t)(blockIdx.x * 8 + row) * H_DIM + c4);
    }
    __syncthreads();

    const int t = blockIdx.x * 8 + warp;

    float acc0 = 0.f, acc1 = 0.f;
#pragma unroll 8
    for (int h = 0; h < H_DIM; h++) {
        float xv = xs[warp][h];
        acc0 += xv * gw[h * E_EXP + lane];
        acc1 += xv * gw[h * E_EXP + lane + 32];
    }
    float sc0 = 1.f / (1.f + expf(-acc0));
    float sc1 = 1.f / (1.f + expf(-acc1));
    float s0 = sc0 + bias[lane];
    float s1 = sc1 + bias[lane + 32];

    float m1a = s0, m2a = -INFINITY;
    float m1b = s1, m2b = -INFINITY;
#pragma unroll
    for (int off = 4; off >= 1; off >>= 1) {
        float o1 = __shfl_xor_sync(FULL, m1a, off);
        float o2 = __shfl_xor_sync(FULL, m2a, off);
        if (o1 > m1a) { m2a = fmaxf(m1a, o2); m1a = o1; }
        else          { m2a = fmaxf(m2a, o1); }
        o1 = __shfl_xor_sync(FULL, m1b, off);
        o2 = __shfl_xor_sync(FULL, m2b, off);
        if (o1 > m1b) { m2b = fmaxf(m1b, o2); m1b = o1; }
        else          { m2b = fmaxf(m2b, o1); }
    }
    float gsv0 = m1a + m2a;
    float gsv1 = m1b + m2b;

    float gs[NGROUP];
#pragma unroll
    for (int g = 0; g < 4; g++) {
        gs[g]     = __shfl_sync(FULL, gsv0, g * 8);
        gs[4 + g] = __shfl_sync(FULL, gsv1, g * 8);
    }
    bool gsel[NGROUP];
#pragma unroll
    for (int g = 0; g < NGROUP; g++) gsel[g] = false;
#pragma unroll
    for (int it = 0; it < TKG; it++) {
        int bi = -1; float bv = -INFINITY;
#pragma unroll
        for (int g = 0; g < NGROUP; g++)
            if (!gsel[g] && gs[g] > bv) { bv = gs[g]; bi = g; }
        gsel[bi] = true;
    }

    float t0 = gsel[lane >> 3]       ? s0 : -INFINITY;
    float t1 = gsel[(lane >> 3) + 4] ? s1 : -INFINITY;

    int   idxk[TOPK];
    float wvk[TOPK];
    float wsum = 0.f;
#pragma unroll
    for (int k = 0; k < TOPK; k++) {
        float bv; int be;
        if (t0 >= t1) { bv = t0; be = lane; }
        else          { bv = t1; be = lane + 32; }
#pragma unroll
        for (int off = 16; off >= 1; off >>= 1) {
            float ov = __shfl_xor_sync(FULL, bv, off);
            int   oi = __shfl_xor_sync(FULL, be, off);
            if (ov > bv || (ov == bv && oi < be)) { bv = ov; be = oi; }
        }
        float scw = __shfl_sync(FULL, (be & 32) ? sc1 : sc0, be & 31);
        idxk[k] = be;
        wvk[k]  = scw;
        wsum   += scw;
        if (lane == (be & 31)) {
            if (be & 32) t1 = -INFINITY; else t0 = -INFINITY;
        }
    }
    if (lane == 0) {
        float inv = 1.f / wsum;
#pragma unroll
        for (int k = 0; k < TOPK; k++) {
            g_w[t * TOPK + k]    = wvk[k] * inv;
            g_eidx[t * TOPK + k] = idxk[k];
        }
    }
}

// ------------------------------ dispatch -----------------------------------
__global__ __launch_bounds__(256) void dispatch_kernel()
{
    const int e = blockIdx.x, tid = threadIdx.x;
    const int lane = tid & 31, wid = tid >> 5;
    __shared__ int warp_tot[8];
    int base = 0;
    for (int chunk = 0; chunk < A_TOT; chunk += 256) {
        int a = chunk + tid;
        int m = (a < A_TOT && g_eidx[a] == e) ? 1 : 0;
        unsigned bal = __ballot_sync(0xffffffffu, m);
        if (lane == 0) warp_tot[wid] = __popc(bal);
        __syncthreads();
        int woff = 0, tot = 0;
#pragma unroll
        for (int i = 0; i < 8; i++) { if (i < wid) woff += warp_tot[i]; tot += warp_tot[i]; }
        if (m) {
            int pos = base + woff + __popc(bal & ((1u << lane) - 1u));
            if (pos < CAP) g_list[e * CAP + pos] = a;
            g_keep[a] = (pos < CAP) ? 1 : 0;
        }
        base += tot;
        __syncthreads();
    }
    if (tid == 0) g_counts[e] = base < CAP ? base : CAP;
}

// ===========================================================================
// GEMM kernels: 64x64 tile, 256 thr = 8 warps (4M x 2N), warp = 16x32.
// ===========================================================================

__global__ __launch_bounds__(256) void shared_gateup_tc()
{
    __shared__ __align__(16) __nv_bfloat16 sAh[64 * SA], sAl[64 * SA];
    __shared__ __align__(16) __nv_bfloat16 sGh[KC * SB], sGl[KC * SB];
    __shared__ __align__(16) __nv_bfloat16 sUh[KC * SB], sUl[KC * SB];

    const int tid = threadIdx.x, lane = tid & 31, wid = tid >> 5;
    const int gid = lane >> 2, tig = lane & 3;
    const int wm = wid & 3, wn = wid >> 2;
    const int rb = blockIdx.y * 64, cb = blockIdx.x * 64;

    const int ar = tid >> 2, ac8 = (tid & 3) * 8;
    const int bk = tid >> 3, bn8 = (tid & 7) * 8;

    const __nv_bfloat16* aH = g_xs_h + (size_t)(rb + ar) * H_DIM + ac8;
    const __nv_bfloat16* aL = g_xs_l + (size_t)(rb + ar) * H_DIM + ac8;
    const __nv_bfloat16* gH = g_wsgu_h + (size_t)bk * SH_GUP + cb + bn8;
    const __nv_bfloat16* gL = g_wsgu_l + (size_t)bk * SH_GUP + cb + bn8;
    const __nv_bfloat16* uH = gH + SH_ACT;
    const __nv_bfloat16* uL = gL + SH_ACT;

    const uint32_t aBase = (uint32_t)((((wm * 16 + (lane & 15)) * SA) + (lane >> 4) * 8) * 2);
    uint32_t aOffH = (uint32_t)__cvta_generic_to_shared(sAh) + aBase;
    uint32_t aOffL = (uint32_t)__cvta_generic_to_shared(sAl) + aBase;
    const int mB = lane >> 3;
    const uint32_t bBase = (uint32_t)(((((mB & 1) * 8 + (lane & 7)) * SB) + wn * 32 + (mB >> 1) * 8) * 2);
    uint32_t gOffH = (uint32_t)__cvta_generic_to_shared(sGh) + bBase;
    uint32_t gOffL = (uint32_t)__cvta_generic_to_shared(sGl) + bBase;
    uint32_t uOffH = (uint32_t)__cvta_generic_to_shared(sUh) + bBase;
    uint32_t uOffL = (uint32_t)__cvta_generic_to_shared(sUl) + bBase;

    float accG[4][4] = {}, accU[4][4] = {};

    for (int k0 = 0; k0 < H_DIM; k0 += KC) {
        *(uint4*)&sAh[ar * SA + ac8] = *(const uint4*)(aH + k0);
        *(uint4*)&sAl[ar * SA + ac8] = *(const uint4*)(aL + k0);
        *(uint4*)&sGh[bk * SB + bn8] = *(const uint4*)(gH + (size_t)k0 * SH_GUP);
        *(uint4*)&sGl[bk * SB + bn8] = *(const uint4*)(gL + (size_t)k0 * SH_GUP);
        *(uint4*)&sUh[bk * SB + bn8] = *(const uint4*)(uH + (size_t)k0 * SH_GUP);
        *(uint4*)&sUl[bk * SB + bn8] = *(const uint4*)(uL + (size_t)k0 * SH_GUP);
        __syncthreads();
#pragma unroll
        for (int s = 0; s < 2; s++) {
            unsigned ah[4], al[4];
            ldsm4(ah, aOffH + s * 32);
            ldsm4(al, aOffL + s * 32);
            unsigned gh[8], gl[8], uh[8], ul[8];
#pragma unroll
            for (int g = 0; g < 2; g++) {
                uint32_t off = (uint32_t)(s * 16 * SB) * 2 + g * 32;
                ldsm4t(&gh[g * 4], gOffH + off);
                ldsm4t(&gl[g * 4], gOffL + off);
                ldsm4t(&uh[g * 4], uOffH + off);
                ldsm4t(&ul[g * 4], uOffL + off);
            }
#pragma unroll
            for (int t = 0; t < 4; t++) {
                int p = (t >> 1) * 4 + (t & 1) * 2;
                mma_bf16(accG[t], ah[0], ah[1], ah[2], ah[3], gh[p], gh[p + 1]);
                mma_bf16(accG[t], ah[0], ah[1], ah[2], ah[3], gl[p], gl[p + 1]);
                mma_bf16(accG[t], al[0], al[1], al[2], al[3], gh[p], gh[p + 1]);
                mma_bf16(accU[t], ah[0], ah[1], ah[2], ah[3], uh[p], uh[p + 1]);
                mma_bf16(accU[t], ah[0], ah[1], ah[2], ah[3], ul[p], ul[p + 1]);
                mma_bf16(accU[t], al[0], al[1], al[2], al[3], uh[p], uh[p + 1]);
            }
        }
        __syncthreads();
    }
    const int r0 = rb + wm * 16 + gid;
#pragma unroll
    for (int t = 0; t < 4; t++) {
        int c = cb + wn * 32 + t * 8 + tig * 2;
#pragma unroll
        for (int i = 0; i < 2; i++) {
            int r = r0 + i * 8;
            float g0 = accG[t][i * 2], u0 = accU[t][i * 2];
            float g1 = accG[t][i * 2 + 1], u1 = accU[t][i * 2 + 1];
            float a0 = (g0 / (1.f + expf(-g0))) * u0;
            float a1 = (g1 / (1.f + expf(-g1))) * u1;
            unsigned h, l;
            f2hl2(a0, a1, h, l);
            *(unsigned*)&g_acts_h[(size_t)r * SH_ACT + c] = h;
            *(unsigned*)&g_acts_l[(size_t)r * SH_ACT + c] = l;
        }
    }
}

__global__ __launch_bounds__(256) void shared_down_tc(float* __restrict__ out)
{
    __shared__ __align__(16) __nv_bfloat16 sAh[64 * SA], sAl[64 * SA];
    __shared__ __align__(16) __nv_bfloat16 sBh[KC * SB], sBl[KC * SB];

    const int tid = threadIdx.x, lane = tid & 31, wid = tid >> 5;
    const int gid = lane >> 2, tig = lane & 3;
    const int wm = wid & 3, wn = wid >> 2;
    const int rb = blockIdx.y * 64, cb = blockIdx.x * 64;

    const int ar = tid >> 2, ac8 = (tid & 3) * 8;
    const int bk = tid >> 3, bn8 = (tid & 7) * 8;

    const __nv_bfloat16* aH = g_acts_h + (size_t)(rb + ar) * SH_ACT + ac8;
    const __nv_bfloat16* aL = g_acts_l + (size_t)(rb + ar) * SH_ACT + ac8;
    const __nv_bfloat16* bH = g_wsd_h + (size_t)bk * H_DIM + cb + bn8;
    const __nv_bfloat16* bL = g_wsd_l + (size_t)bk * H_DIM + cb + bn8;

    const uint32_t aBase = (uint32_t)((((wm * 16 + (lane & 15)) * SA) + (lane >> 4) * 8) * 2);
    uint32_t aOffH = (uint32_t)__cvta_generic_to_shared(sAh) + aBase;
    uint32_t aOffL = (uint32_t)__cvta_generic_to_shared(sAl) + aBase;
    const int mB = lane >> 3;
    const uint32_t bBase = (uint32_t)(((((mB & 1) * 8 + (lane & 7)) * SB) + wn * 32 + (mB >> 1) * 8) * 2);
    uint32_t bOffH = (uint32_t)__cvta_generic_to_shared(sBh) + bBase;
    uint32_t bOffL = (uint32_t)__cvta_generic_to_shared(sBl) + bBase;

    float acc[4][4] = {};

    for (int k0 = 0; k0 < SH_ACT; k0 += KC) {
        *(uint4*)&sAh[ar * SA + ac8] = *(const uint4*)(aH + k0);
        *(uint4*)&sAl[ar * SA + ac8] = *(const uint4*)(aL + k0);
        *(uint4*)&sBh[bk * SB + bn8] = *(const uint4*)(bH + (size_t)k0 * H_DIM);
        *(uint4*)&sBl[bk * SB + bn8] = *(const uint4*)(bL + (size_t)k0 * H_DIM);
        __syncthreads();
#pragma unroll
        for (int s = 0; s < 2; s++) {
            unsigned ah[4], al[4];
            ldsm4(ah, aOffH + s * 32);
            ldsm4(al, aOffL + s * 32);
            unsigned bh[8], bl[8];
#pragma unroll
            for (int g = 0; g < 2; g++) {
                uint32_t off = (uint32_t)(s * 16 * SB) * 2 + g * 32;
                ldsm4t(&bh[g * 4], bOffH + off);
                ldsm4t(&bl[g * 4], bOffL + off);
            }
#pragma unroll
            for (int t = 0; t < 4; t++) {
                int p = (t >> 1) * 4 + (t & 1) * 2;
                mma_bf16(acc[t], ah[0], ah[1], ah[2], ah[3], bh[p], bh[p + 1]);
                mma_bf16(acc[t], ah[0], ah[1], ah[2], ah[3], bl[p], bl[p + 1]);
                mma_bf16(acc[t], al[0], al[1], al[2], al[3], bh[p], bh[p + 1]);
            }
        }
        __syncthreads();
    }
    const int r0 = rb + wm * 16 + gid;
#pragma unroll
    for (int t = 0; t < 4; t++) {
        int c = cb + wn * 32 + t * 8 + tig * 2;
        out[(size_t)(r0    ) * H_DIM + c + 0] = acc[t][0];
        out[(size_t)(r0    ) * H_DIM + c + 1] = acc[t][1];
        out[(size_t)(r0 + 8) * H_DIM + c + 0] = acc[t][2];
        out[(size_t)(r0 + 8) * H_DIM + c + 1] = acc[t][3];
    }
}

// ------- routed gate_up: fp32 weights, inline hi/lo conversion -------------
__global__ __launch_bounds__(256) void routed_gateup_tc(
    const float* __restrict__ Wall /*[E,H,1024] fp32*/)
{
    const int e = blockIdx.z;
    const int cnt = g_counts[e];
    const int r0b = blockIdx.y * 64;
    if (r0b >= cnt) return;

    __shared__ __align__(16) __nv_bfloat16 sAh[64 * SA], sAl[64 * SA];
    __shared__ __align__(16) __nv_bfloat16 sGh[KC * SB], sGl[KC * SB];
    __shared__ __align__(16) __nv_bfloat16 sUh[KC * SB], sUl[KC * SB];

    const int tid = threadIdx.x, lane = tid & 31, wid = tid >> 5;
    const int gid = lane >> 2, tig = lane & 3;
    const int wm = wid & 3, wn = wid >> 2;
    const int cb = blockIdx.x * 64;

    const int ar = tid >> 2, ac8 = (tid & 3) * 8;
    const int bk = tid >> 3, bn8 = (tid & 7) * 8;

    int tok = 0;
    {
        int r = r0b + ar;
        if (r < cnt) tok = g_list[e * CAP + r] / TOPK;
    }
    const __nv_bfloat16* aH = g_xs_h + (size_t)tok * H_DIM + ac8;
    const __nv_bfloat16* aL = g_xs_l + (size_t)tok * H_DIM + ac8;
    const float* gW = Wall + (size_t)e * H_DIM * GUP_COLS + (size_t)bk * GUP_COLS + cb + bn8;
    const float* uW = gW + I_DIM;

    const uint32_t aBase = (uint32_t)((((wm * 16 + (lane & 15)) * SA) + (lane >> 4) * 8) * 2);
    uint32_t aOffH = (uint32_t)__cvta_generic_to_shared(sAh) + aBase;
    uint32_t aOffL = (uint32_t)__cvta_generic_to_shared(sAl) + aBase;
    const int mB = lane >> 3;
    const uint32_t bBase = (uint32_t)(((((mB & 1) * 8 + (lane & 7)) * SB) + wn * 32 + (mB >> 1) * 8) * 2);
    uint32_t gOffH = (uint32_t)__cvta_generic_to_shared(sGh) + bBase;
    uint32_t gOffL = (uint32_t)__cvta_generic_to_shared(sGl) + bBase;
    uint32_t uOffH = (uint32_t)__cvta_generic_to_shared(sUh) + bBase;
    uint32_t uOffL = (uint32_t)__cvta_generic_to_shared(sUl) + bBase;

    float accG[4][4] = {}, accU[4][4] = {};

    for (int k0 = 0; k0 < H_DIM; k0 += KC) {
        *(uint4*)&sAh[ar * SA + ac8] = *(const uint4*)(aH + k0);
        *(uint4*)&sAl[ar * SA + ac8] = *(const uint4*)(aL + k0);
        {
            const float* gp = gW + (size_t)k0 * GUP_COLS;
            const float* up = uW + (size_t)k0 * GUP_COLS;
            float4 v0 = *(const float4*)gp;
            float4 v1 = *(const float4*)(gp + 4);
            unsigned h01, l01, h23, l23;
            f2hl2(v0.x, v0.y, h01, l01); f2hl2(v0.z, v0.w, h23, l23);
            *(uint2*)&sGh[bk * SB + bn8] = make_uint2(h01, h23);
            *(uint2*)&sGl[bk * SB + bn8] = make_uint2(l01, l23);
            f2hl2(v1.x, v1.y, h01, l01); f2hl2(v1.z, v1.w, h23, l23);
            *(uint2*)&sGh[bk * SB + bn8 + 4] = make_uint2(h01, h23);
            *(uint2*)&sGl[bk * SB + bn8 + 4] = make_uint2(l01, l23);
            v0 = *(const float4*)up;
            v1 = *(const float4*)(up + 4);
            f2hl2(v0.x, v0.y, h01, l01); f2hl2(v0.z, v0.w, h23, l23);
            *(uint2*)&sUh[bk * SB + bn8] = make_uint2(h01, h23);
            *(uint2*)&sUl[bk * SB + bn8] = make_uint2(l01, l23);
            f2hl2(v1.x, v1.y, h01, l01); f2hl2(v1.z, v1.w, h23, l23);
            *(uint2*)&sUh[bk * SB + bn8 + 4] = make_uint2(h01, h23);
            *(uint2*)&sUl[bk * SB + bn8 + 4] = make_uint2(l01, l23);
        }
        __syncthreads();
#pragma unroll
        for (int s = 0; s < 2; s++) {
            unsigned ah[4], al[4];
            ldsm4(ah, aOffH + s * 32);
            ldsm4(al, aOffL + s * 32);
            unsigned gh[8], gl[8], uh[8], ul[8];
#pragma unroll
            for (int g = 0; g < 2; g++) {
                uint32_t off = (uint32_t)(s * 16 * SB) * 2 + g * 32;
                ldsm4t(&gh[g * 4], gOffH + off);
                ldsm4t(&gl[g * 4], gOffL + off);
                ldsm4t(&uh[g * 4], uOffH + off);
                ldsm4t(&ul[g * 4], uOffL + off);
            }
#pragma unroll
            for (int t = 0; t < 4; t++) {
                int p = (t >> 1) * 4 + (t & 1) * 2;
                mma_bf16(accG[t], ah[0], ah[1], ah[2], ah[3], gh[p], gh[p + 1]);
                mma_bf16(accG[t], ah[0], ah[1], ah[2], ah[3], gl[p], gl[p + 1]);
                mma_bf16(accG[t], al[0], al[1], al[2], al[3], gh[p], gh[p + 1]);
                mma_bf16(accU[t], ah[0], ah[1], ah[2], ah[3], uh[p], uh[p + 1]);
                mma_bf16(accU[t], ah[0], ah[1], ah[2], ah[3], ul[p], ul[p + 1]);
                mma_bf16(accU[t], al[0], al[1], al[2], al[3], uh[p], uh[p + 1]);
            }
        }
        __syncthreads();
    }
    const int rw = wm * 16 + gid;
#pragma unroll
    for (int t = 0; t < 4; t++) {
        int c = cb + wn * 32 + t * 8 + tig * 2;
#pragma unroll
        for (int i = 0; i < 2; i++) {
            int r = r0b + rw + i * 8;
            if (r < cnt) {
                float g0 = accG[t][i * 2], u0 = accU[t][i * 2];
                float g1 = accG[t][i * 2 + 1], u1 = accU[t][i * 2 + 1];
                float a0 = (g0 / (1.f + expf(-g0))) * u0;
                float a1 = (g1 / (1.f + expf(-g1))) * u1;
                unsigned h, l;
                f2hl2(a0, a1, h, l);
                *(unsigned*)&g_actr_h[((size_t)e * CAP + r) * I_DIM + c] = h;
                *(unsigned*)&g_actr_l[((size_t)e * CAP + r) * I_DIM + c] = l;
            }
        }
    }
}

// ------- routed down: fp32 weights, inline hi/lo conversion ----------------
__global__ __launch_bounds__(256) void routed_down_tc(
    const float* __restrict__ Wall /*[E,512,1024] fp32*/)
{
    const int e = blockIdx.z;
    const int cnt = g_counts[e];
    const int r0b = blockIdx.y * 64;
    if (r0b >= cnt) return;

    __shared__ __align__(16) __nv_bfloat16 sAh[64 * SA], sAl[64 * SA];
    __shared__ __align__(16) __nv_bfloat16 sBh[KC * SB], sBl[KC * SB];

    const int tid = threadIdx.x, lane = tid & 31, wid = tid >> 5;
    const int gid = lane >> 2, tig = lane & 3;
    const int wm = wid & 3, wn = wid >> 2;
    const int cb = blockIdx.x * 64;

    const int ar = tid >> 2, ac8 = (tid & 3) * 8;
    const int bk = tid >> 3, bn8 = (tid & 7) * 8;

    const __nv_bfloat16* aH = g_actr_h + ((size_t)e * CAP + (r0b + ar)) * I_DIM + ac8;
    const __nv_bfloat16* aL = g_actr_l + ((size_t)e * CAP + (r0b + ar)) * I_DIM + ac8;
    const float* bW = Wall + (size_t)e * I_DIM * H_DIM + (size_t)bk * H_DIM + cb + bn8;

    const uint32_t aBase = (uint32_t)((((wm * 16 + (lane & 15)) * SA) + (lane >> 4) * 8) * 2);
    uint32_t aOffH = (uint32_t)__cvta_generic_to_shared(sAh) + aBase;
    uint32_t aOffL = (uint32_t)__cvta_generic_to_shared(sAl) + aBase;
    const int mB = lane >> 3;
    const uint32_t bBase = (uint32_t)(((((mB & 1) * 8 + (lane & 7)) * SB) + wn * 32 + (mB >> 1) * 8) * 2);
    uint32_t bOffH = (uint32_t)__cvta_generic_to_shared(sBh) + bBase;
    uint32_t bOffL = (uint32_t)__cvta_generic_to_shared(sBl) + bBase;

    float acc[4][4] = {};

    for (int k0 = 0; k0 < I_DIM; k0 += KC) {
        *(uint4*)&sAh[ar * SA + ac8] = *(const uint4*)(aH + k0);
        *(uint4*)&sAl[ar * SA + ac8] = *(const uint4*)(aL + k0);
        {
            const float* bp = bW + (size_t)k0 * H_DIM;
            float4 v0 = *(const float4*)bp;
            float4 v1 = *(const float4*)(bp + 4);
            unsigned h01, l01, h23, l23;
            f2hl2(v0.x, v0.y, h01, l01); f2hl2(v0.z, v0.w, h23, l23);
            *(uint2*)&sBh[bk * SB + bn8] = make_uint2(h01, h23);
            *(uint2*)&sBl[bk * SB + bn8] = make_uint2(l01, l23);
            f2hl2(v1.x, v1.y, h01, l01); f2hl2(v1.z, v1.w, h23, l23);
            *(uint2*)&sBh[bk * SB + bn8 + 4] = make_uint2(h01, h23);
            *(uint2*)&sBl[bk * SB + bn8 + 4] = make_uint2(l01, l23);
        }
        __syncthreads();
#pragma unroll
        for (int s = 0; s < 2; s++) {
            unsigned ah[4], al[4];
            ldsm4(ah, aOffH + s * 32);
            ldsm4(al, aOffL + s * 32);
            unsigned bh[8], bl[8];
#pragma unroll
            for (int g = 0; g < 2; g++) {
                uint32_t off = (uint32_t)(s * 16 * SB) * 2 + g * 32;
                ldsm4t(&bh[g * 4], bOffH + off);
                ldsm4t(&bl[g * 4], bOffL + off);
            }
#pragma unroll
            for (int t = 0; t < 4; t++) {
                int p = (t >> 1) * 4 + (t & 1) * 2;
                mma_bf16(acc[t], ah[0], ah[1], ah[2], ah[3], bh[p], bh[p + 1]);
                mma_bf16(acc[t], ah[0], ah[1], ah[2], ah[3], bl[p], bl[p + 1]);
                mma_bf16(acc[t], al[0], al[1], al[2], al[3], bh[p], bh[p + 1]);
            }
        }
        __syncthreads();
    }
    const int rw = wm * 16 + gid;
#pragma unroll
    for (int t = 0; t < 4; t++) {
        int c = cb + wn * 32 + t * 8 + tig * 2;
#pragma unroll
        for (int i = 0; i < 2; i++) {
            int r = r0b + rw + i * 8;
            if (r < cnt) {
                int a = g_list[e * CAP + r];
                g_ybuf[(size_t)a * H_DIM + c + 0] = acc[t][i * 2 + 0];
                g_ybuf[(size_t)a * H_DIM + c + 1] = acc[t][i * 2 + 1];
            }
        }
    }
}

// ------------------------------- combine -----------------------------------
__global__ __launch_bounds__(256) void combine_kernel(float* __restrict__ out)
{
    const int t = blockIdx.x;
    const int h4 = threadIdx.x * 4;
    float4 o = *(float4*)(out + (size_t)t * H_DIM + h4);
    float r0 = o.x, r1 = o.y, r2 = o.z, r3 = o.w;
#pragma unroll
    for (int k = 0; k < TOPK; k++) {
        int a = t * TOPK + k;
        if (g_keep[a]) {
            float wv = g_w[a] * SCALE_F;
            float4 y = *(const float4*)(g_ybuf + (size_t)a * H_DIM + h4);
            r0 += wv * y.x; r1 += wv * y.y; r2 += wv * y.z; r3 += wv * y.w;
        }
    }
    *(float4*)(out + (size_t)t * H_DIM + h4) = make_float4(r0, r1, r2, r3);
}

// ------------------------------- launcher ----------------------------------
extern "C" void kernel_launch(void* const* d_in, const int* in_sizes, int n_in,
                              void* d_out, int out_size)
{
    const float* x          = (const float*)d_in[0];
    const float* gate_w     = (const float*)d_in[1];
    const float* e_bias     = (const float*)d_in[2];
    const float* w_gate_up  = (const float*)d_in[3];
    const float* w_down     = (const float*)d_in[4];
    const float* ws_gate_up = (const float*)d_in[5];
    const float* ws_down    = (const float*)d_in[6];
    float* out = (float*)d_out;

    __nv_bfloat16 *xs_h, *xs_l, *wsgu_h, *wsgu_l, *wsd_h, *wsd_l;
    cudaGetSymbolAddress((void**)&xs_h, g_xs_h);
    cudaGetSymbolAddress((void**)&xs_l, g_xs_l);
    cudaGetSymbolAddress((void**)&wsgu_h, g_wsgu_h);
    cudaGetSymbolAddress((void**)&wsgu_l, g_wsgu_l);
    cudaGetSymbolAddress((void**)&wsd_h, g_wsd_h);
    cudaGetSymbolAddress((void**)&wsd_l, g_wsd_l);

    auto split = [](const float* s, __nv_bfloat16* h, __nv_bfloat16* l, size_t n) {
        int n4 = (int)(n / 4);
        split_kernel<<<(n4 + 255) / 256, 256>>>((const float4*)s, (uint2*)h, (uint2*)l, n4);
    };

    split(x,          xs_h,   xs_l,   (size_t)T_TOK * H_DIM);
    split(ws_gate_up, wsgu_h, wsgu_l, (size_t)H_DIM * SH_GUP);
    split(ws_down,    wsd_h,  wsd_l,  (size_t)SH_ACT * H_DIM);

    router_kernel<<<T_TOK / 8, 256>>>(x, gate_w, e_bias);
    dispatch_kernel<<<E_EXP, 256>>>();

    shared_gateup_tc<<<dim3(SH_ACT / 64, T_TOK / 64), 256>>>();
    shared_down_tc<<<dim3(H_DIM / 64, T_TOK / 64), 256>>>(out);
    routed_gateup_tc<<<dim3(I_DIM / 64, CAP / 64, E_EXP), 256>>>(w_gate_up);
    routed_down_tc<<<dim3(H_DIM / 64, CAP / 64, E_EXP), 256>>>(w_down);
    combine_kernel<<<T_TOK, 256>>>(out);
}

// round 10
// speedup vs baseline: 1.8345x; 1.0732x over previous
#include <cuda_runtime.h>
#include <cuda_bf16.h>
#include <cstdint>
#include <math.h>

// ---------------------------------------------------------------------------
// DeepseekV2 MoE.
//  - x + shared weights: one-time hi/lo bf16 plane splits.
//  - Shared GEMMs: 64x64 tiles, ldmatrix + m16n8k16 3-term hi/lo MMA.
//  - Routed GEMMs: M=128 dual-A-tile blocks (256 thr), fp32 weights converted
//    inline in the B producer -> expert weights read exactly once.
//  - Router: 4 tokens/block, sliced-dot logits + warp-shuffle grouped top-k.
// ---------------------------------------------------------------------------

#define T_TOK   1024
#define H_DIM   1024
#define E_EXP   64
#define I_DIM   512
#define TOPK    6
#define NGROUP  8
#define TKG     3
#define CAP     256
#define A_TOT   (T_TOK * TOPK)
#define SCALE_F 2.5f
#define GUP_COLS (2 * I_DIM)
#define SH_ACT   1024
#define SH_GUP   2048

#define KC 32
#define SA 40
#define SB 72

// ------------------------------- scratch -----------------------------------
__device__ float g_w[A_TOT];
__device__ int   g_eidx[A_TOT];
__device__ int   g_counts[E_EXP];
__device__ int   g_list[E_EXP * CAP];
__device__ int   g_keep[A_TOT];

__device__ __nv_bfloat16 g_xs_h[T_TOK * H_DIM];
__device__ __nv_bfloat16 g_xs_l[T_TOK * H_DIM];
__device__ __nv_bfloat16 g_wsgu_h[H_DIM * SH_GUP];
__device__ __nv_bfloat16 g_wsgu_l[H_DIM * SH_GUP];
__device__ __nv_bfloat16 g_wsd_h[SH_ACT * H_DIM];
__device__ __nv_bfloat16 g_wsd_l[SH_ACT * H_DIM];
__device__ __nv_bfloat16 g_acts_h[T_TOK * SH_ACT];
__device__ __nv_bfloat16 g_acts_l[T_TOK * SH_ACT];
__device__ __nv_bfloat16 g_actr_h[(size_t)E_EXP * CAP * I_DIM];
__device__ __nv_bfloat16 g_actr_l[(size_t)E_EXP * CAP * I_DIM];
__device__ float g_ybuf[(size_t)A_TOT * H_DIM];

// ------------------------------- helpers -----------------------------------
__device__ __forceinline__ unsigned pack2(__nv_bfloat16 a, __nv_bfloat16 b) {
    __nv_bfloat162 t = __halves2bfloat162(a, b);
    return *(unsigned*)&t;
}

__device__ __forceinline__ void f2hl2(float x, float y, unsigned& h, unsigned& l) {
    __nv_bfloat16 h0 = __float2bfloat16(x), h1 = __float2bfloat16(y);
    __nv_bfloat16 l0 = __float2bfloat16(x - __bfloat162float(h0));
    __nv_bfloat16 l1 = __float2bfloat16(y - __bfloat162float(h1));
    h = pack2(h0, h1);
    l = pack2(l0, l1);
}

__device__ __forceinline__ void mma_bf16(float c[4],
    unsigned a0, unsigned a1, unsigned a2, unsigned a3,
    unsigned b0, unsigned b1)
{
    asm volatile(
        "mma.sync.aligned.m16n8k16.row.col.f32.bf16.bf16.f32 "
        "{%0,%1,%2,%3}, {%4,%5,%6,%7}, {%8,%9}, {%0,%1,%2,%3};"
        : "+f"(c[0]), "+f"(c[1]), "+f"(c[2]), "+f"(c[3])
        : "r"(a0), "r"(a1), "r"(a2), "r"(a3), "r"(b0), "r"(b1));
}

__device__ __forceinline__ void ldsm4(unsigned* r, uint32_t addr) {
    asm volatile("ldmatrix.sync.aligned.m8n8.x4.shared.b16 {%0,%1,%2,%3}, [%4];"
        : "=r"(r[0]), "=r"(r[1]), "=r"(r[2]), "=r"(r[3]) : "r"(addr));
}
__device__ __forceinline__ void ldsm4t(unsigned* r, uint32_t addr) {
    asm volatile("ldmatrix.sync.aligned.m8n8.x4.trans.shared.b16 {%0,%1,%2,%3}, [%4];"
        : "=r"(r[0]), "=r"(r[1]), "=r"(r[2]), "=r"(r[3]) : "r"(addr));
}

// ------------------------------- split -------------------------------------
__global__ __launch_bounds__(256) void split_kernel(
    const float4* __restrict__ src, uint2* __restrict__ hi, uint2* __restrict__ lo, int n4)
{
    int i = blockIdx.x * 256 + threadIdx.x;
    if (i >= n4) return;
    float4 v = src[i];
    unsigned h01, l01, h23, l23;
    f2hl2(v.x, v.y, h01, l01);
    f2hl2(v.z, v.w, h23, l23);
    hi[i] = make_uint2(h01, h23);
    lo[i] = make_uint2(l01, l23);
}

// ---------------- router: 4 tokens/block, sliced logits --------------------
__global__ __launch_bounds__(256) void router_kernel(
    const float* __restrict__ x, const float* __restrict__ gw,
    const float* __restrict__ bias)
{
    __shared__ float xs[4][H_DIM];       // 16 KB
    __shared__ float part[4][4][E_EXP];  // 4 KB  [token][slice][expert]
    const int tid = threadIdx.x;
    const unsigned FULL = 0xffffffffu;

    for (int i = tid; i < 4 * (H_DIM / 4); i += 256) {
        int row = i >> 8, c4 = (i & 255) * 4;
        *(float4*)&xs[row][c4] = *(const float4*)(x + (size_t)(blockIdx.x * 4 + row) * H_DIM + c4);
    }
    __syncthreads();

    // logits partials: thread (slice, expert)
    {
        const int e = tid & 63, sl = tid >> 6;
        const float* gp = gw + e;
        float a0 = 0.f, a1 = 0.f, a2 = 0.f, a3 = 0.f;
        const int h0 = sl * 256;
#pragma unroll 8
        for (int h = h0; h < h0 + 256; h++) {
            float gv = gp[h * E_EXP];
            a0 += xs[0][h] * gv;
            a1 += xs[1][h] * gv;
            a2 += xs[2][h] * gv;
            a3 += xs[3][h] * gv;
        }
        part[0][sl][e] = a0;
        part[1][sl][e] = a1;
        part[2][sl][e] = a2;
        part[3][sl][e] = a3;
    }
    __syncthreads();

    // selection: warps 0..3, one token each
    const int warp = tid >> 5, lane = tid & 31;
    if (warp >= 4) return;
    const int t = blockIdx.x * 4 + warp;

    float lg0 = part[warp][0][lane]      + part[warp][1][lane]
              + part[warp][2][lane]      + part[warp][3][lane];
    float lg1 = part[warp][0][lane + 32] + part[warp][1][lane + 32]
              + part[warp][2][lane + 32] + part[warp][3][lane + 32];
    float sc0 = 1.f / (1.f + expf(-lg0));
    float sc1 = 1.f / (1.f + expf(-lg1));
    float s0 = sc0 + bias[lane];
    float s1 = sc1 + bias[lane + 32];

    float m1a = s0, m2a = -INFINITY;
    float m1b = s1, m2b = -INFINITY;
#pragma unroll
    for (int off = 4; off >= 1; off >>= 1) {
        float o1 = __shfl_xor_sync(FULL, m1a, off);
        float o2 = __shfl_xor_sync(FULL, m2a, off);
        if (o1 > m1a) { m2a = fmaxf(m1a, o2); m1a = o1; }
        else          { m2a = fmaxf(m2a, o1); }
        o1 = __shfl_xor_sync(FULL, m1b, off);
        o2 = __shfl_xor_sync(FULL, m2b, off);
        if (o1 > m1b) { m2b = fmaxf(m1b, o2); m1b = o1; }
        else          { m2b = fmaxf(m2b, o1); }
    }
    float gsv0 = m1a + m2a;
    float gsv1 = m1b + m2b;

    float gs[NGROUP];
#pragma unroll
    for (int g = 0; g < 4; g++) {
        gs[g]     = __shfl_sync(FULL, gsv0, g * 8);
        gs[4 + g] = __shfl_sync(FULL, gsv1, g * 8);
    }
    bool gsel[NGROUP];
#pragma unroll
    for (int g = 0; g < NGROUP; g++) gsel[g] = false;
#pragma unroll
    for (int it = 0; it < TKG; it++) {
        int bi = -1; float bv = -INFINITY;
#pragma unroll
        for (int g = 0; g < NGROUP; g++)
            if (!gsel[g] && gs[g] > bv) { bv = gs[g]; bi = g; }
        gsel[bi] = true;
    }

    float t0 = gsel[lane >> 3]       ? s0 : -INFINITY;
    float t1 = gsel[(lane >> 3) + 4] ? s1 : -INFINITY;

    int   idxk[TOPK];
    float wvk[TOPK];
    float wsum = 0.f;
#pragma unroll
    for (int k = 0; k < TOPK; k++) {
        float bv; int be;
        if (t0 >= t1) { bv = t0; be = lane; }
        else          { bv = t1; be = lane + 32; }
#pragma unroll
        for (int off = 16; off >= 1; off >>= 1) {
            float ov = __shfl_xor_sync(FULL, bv, off);
            int   oi = __shfl_xor_sync(FULL, be, off);
            if (ov > bv || (ov == bv && oi < be)) { bv = ov; be = oi; }
        }
        float scw = __shfl_sync(FULL, (be & 32) ? sc1 : sc0, be & 31);
        idxk[k] = be;
        wvk[k]  = scw;
        wsum   += scw;
        if (lane == (be & 31)) {
            if (be & 32) t1 = -INFINITY; else t0 = -INFINITY;
        }
    }
    if (lane == 0) {
        float inv = 1.f / wsum;
#pragma unroll
        for (int k = 0; k < TOPK; k++) {
            g_w[t * TOPK + k]    = wvk[k] * inv;
            g_eidx[t * TOPK + k] = idxk[k];
        }
    }
}

// ------------------------------ dispatch -----------------------------------
__global__ __launch_bounds__(256) void dispatch_kernel()
{
    const int e = blockIdx.x, tid = threadIdx.x;
    const int lane = tid & 31, wid = tid >> 5;
    __shared__ int warp_tot[8];
    int base = 0;
    for (int chunk = 0; chunk < A_TOT; chunk += 256) {
        int a = chunk + tid;
        int m = (a < A_TOT && g_eidx[a] == e) ? 1 : 0;
        unsigned bal = __ballot_sync(0xffffffffu, m);
        if (lane == 0) warp_tot[wid] = __popc(bal);
        __syncthreads();
        int woff = 0, tot = 0;
#pragma unroll
        for (int i = 0; i < 8; i++) { if (i < wid) woff += warp_tot[i]; tot += warp_tot[i]; }
        if (m) {
            int pos = base + woff + __popc(bal & ((1u << lane) - 1u));
            if (pos < CAP) g_list[e * CAP + pos] = a;
            g_keep[a] = (pos < CAP) ? 1 : 0;
        }
        base += tot;
        __syncthreads();
    }
    if (tid == 0) g_counts[e] = base < CAP ? base : CAP;
}

// ===========================================================================
// Shared GEMMs: 64x64 tile, 256 thr = 8 warps (4M x 2N), warp = 16x32.
// ===========================================================================

__global__ __launch_bounds__(256) void shared_gateup_tc()
{
    __shared__ __align__(16) __nv_bfloat16 sAh[64 * SA], sAl[64 * SA];
    __shared__ __align__(16) __nv_bfloat16 sGh[KC * SB], sGl[KC * SB];
    __shared__ __align__(16) __nv_bfloat16 sUh[KC * SB], sUl[KC * SB];

    const int tid = threadIdx.x, lane = tid & 31, wid = tid >> 5;
    const int gid = lane >> 2, tig = lane & 3;
    const int wm = wid & 3, wn = wid >> 2;
    const int rb = blockIdx.y * 64, cb = blockIdx.x * 64;

    const int ar = tid >> 2, ac8 = (tid & 3) * 8;
    const int bk = tid >> 3, bn8 = (tid & 7) * 8;

    const __nv_bfloat16* aH = g_xs_h + (size_t)(rb + ar) * H_DIM + ac8;
    const __nv_bfloat16* aL = g_xs_l + (size_t)(rb + ar) * H_DIM + ac8;
    const __nv_bfloat16* gH = g_wsgu_h + (size_t)bk * SH_GUP + cb + bn8;
    const __nv_bfloat16* gL = g_wsgu_l + (size_t)bk * SH_GUP + cb + bn8;
    const __nv_bfloat16* uH = gH + SH_ACT;
    const __nv_bfloat16* uL = gL + SH_ACT;

    const uint32_t aBase = (uint32_t)((((wm * 16 + (lane & 15)) * SA) + (lane >> 4) * 8) * 2);
    uint32_t aOffH = (uint32_t)__cvta_generic_to_shared(sAh) + aBase;
    uint32_t aOffL = (uint32_t)__cvta_generic_to_shared(sAl) + aBase;
    const int mB = lane >> 3;
    const uint32_t bBase = (uint32_t)(((((mB & 1) * 8 + (lane & 7)) * SB) + wn * 32 + (mB >> 1) * 8) * 2);
    uint32_t gOffH = (uint32_t)__cvta_generic_to_shared(sGh) + bBase;
    uint32_t gOffL = (uint32_t)__cvta_generic_to_shared(sGl) + bBase;
    uint32_t uOffH = (uint32_t)__cvta_generic_to_shared(sUh) + bBase;
    uint32_t uOffL = (uint32_t)__cvta_generic_to_shared(sUl) + bBase;

    float accG[4][4] = {}, accU[4][4] = {};

    for (int k0 = 0; k0 < H_DIM; k0 += KC) {
        *(uint4*)&sAh[ar * SA + ac8] = *(const uint4*)(aH + k0);
        *(uint4*)&sAl[ar * SA + ac8] = *(const uint4*)(aL + k0);
        *(uint4*)&sGh[bk * SB + bn8] = *(const uint4*)(gH + (size_t)k0 * SH_GUP);
        *(uint4*)&sGl[bk * SB + bn8] = *(const uint4*)(gL + (size_t)k0 * SH_GUP);
        *(uint4*)&sUh[bk * SB + bn8] = *(const uint4*)(uH + (size_t)k0 * SH_GUP);
        *(uint4*)&sUl[bk * SB + bn8] = *(const uint4*)(uL + (size_t)k0 * SH_GUP);
        __syncthreads();
#pragma unroll
        for (int s = 0; s < 2; s++) {
            unsigned ah[4], al[4];
            ldsm4(ah, aOffH + s * 32);
            ldsm4(al, aOffL + s * 32);
            unsigned gh[8], gl[8], uh[8], ul[8];
#pragma unroll
            for (int g = 0; g < 2; g++) {
                uint32_t off = (uint32_t)(s * 16 * SB) * 2 + g * 32;
                ldsm4t(&gh[g * 4], gOffH + off);
                ldsm4t(&gl[g * 4], gOffL + off);
                ldsm4t(&uh[g * 4], uOffH + off);
                ldsm4t(&ul[g * 4], uOffL + off);
            }
#pragma unroll
            for (int t = 0; t < 4; t++) {
                int p = (t >> 1) * 4 + (t & 1) * 2;
                mma_bf16(accG[t], ah[0], ah[1], ah[2], ah[3], gh[p], gh[p + 1]);
                mma_bf16(accG[t], ah[0], ah[1], ah[2], ah[3], gl[p], gl[p + 1]);
                mma_bf16(accG[t], al[0], al[1], al[2], al[3], gh[p], gh[p + 1]);
                mma_bf16(accU[t], ah[0], ah[1], ah[2], ah[3], uh[p], uh[p + 1]);
                mma_bf16(accU[t], ah[0], ah[1], ah[2], ah[3], ul[p], ul[p + 1]);
                mma_bf16(accU[t], al[0], al[1], al[2], al[3], uh[p], uh[p + 1]);
            }
        }
        __syncthreads();
    }
    const int r0 = rb + wm * 16 + gid;
#pragma unroll
    for (int t = 0; t < 4; t++) {
        int c = cb + wn * 32 + t * 8 + tig * 2;
#pragma unroll
        for (int i = 0; i < 2; i++) {
            int r = r0 + i * 8;
            float g0 = accG[t][i * 2], u0 = accU[t][i * 2];
            float g1 = accG[t][i * 2 + 1], u1 = accU[t][i * 2 + 1];
            float a0 = (g0 / (1.f + expf(-g0))) * u0;
            float a1 = (g1 / (1.f + expf(-g1))) * u1;
            unsigned h, l;
            f2hl2(a0, a1, h, l);
            *(unsigned*)&g_acts_h[(size_t)r * SH_ACT + c] = h;
            *(unsigned*)&g_acts_l[(size_t)r * SH_ACT + c] = l;
        }
    }
}

__global__ __launch_bounds__(256) void shared_down_tc(float* __restrict__ out)
{
    __shared__ __align__(16) __nv_bfloat16 sAh[64 * SA], sAl[64 * SA];
    __shared__ __align__(16) __nv_bfloat16 sBh[KC * SB], sBl[KC * SB];

    const int tid = threadIdx.x, lane = tid & 31, wid = tid >> 5;
    const int gid = lane >> 2, tig = lane & 3;
    const int wm = wid & 3, wn = wid >> 2;
    const int rb = blockIdx.y * 64, cb = blockIdx.x * 64;

    const int ar = tid >> 2, ac8 = (tid & 3) * 8;
    const int bk = tid >> 3, bn8 = (tid & 7) * 8;

    const __nv_bfloat16* aH = g_acts_h + (size_t)(rb + ar) * SH_ACT + ac8;
    const __nv_bfloat16* aL = g_acts_l + (size_t)(rb + ar) * SH_ACT + ac8;
    const __nv_bfloat16* bH = g_wsd_h + (size_t)bk * H_DIM + cb + bn8;
    const __nv_bfloat16* bL = g_wsd_l + (size_t)bk * H_DIM + cb + bn8;

    const uint32_t aBase = (uint32_t)((((wm * 16 + (lane & 15)) * SA) + (lane >> 4) * 8) * 2);
    uint32_t aOffH = (uint32_t)__cvta_generic_to_shared(sAh) + aBase;
    uint32_t aOffL = (uint32_t)__cvta_generic_to_shared(sAl) + aBase;
    const int mB = lane >> 3;
    const uint32_t bBase = (uint32_t)(((((mB & 1) * 8 + (lane & 7)) * SB) + wn * 32 + (mB >> 1) * 8) * 2);
    uint32_t bOffH = (uint32_t)__cvta_generic_to_shared(sBh) + bBase;
    uint32_t bOffL = (uint32_t)__cvta_generic_to_shared(sBl) + bBase;

    float acc[4][4] = {};

    for (int k0 = 0; k0 < SH_ACT; k0 += KC) {
        *(uint4*)&sAh[ar * SA + ac8] = *(const uint4*)(aH + k0);
        *(uint4*)&sAl[ar * SA + ac8] = *(const uint4*)(aL + k0);
        *(uint4*)&sBh[bk * SB + bn8] = *(const uint4*)(bH + (size_t)k0 * H_DIM);
        *(uint4*)&sBl[bk * SB + bn8] = *(const uint4*)(bL + (size_t)k0 * H_DIM);
        __syncthreads();
#pragma unroll
        for (int s = 0; s < 2; s++) {
            unsigned ah[4], al[4];
            ldsm4(ah, aOffH + s * 32);
            ldsm4(al, aOffL + s * 32);
            unsigned bh[8], bl[8];
#pragma unroll
            for (int g = 0; g < 2; g++) {
                uint32_t off = (uint32_t)(s * 16 * SB) * 2 + g * 32;
                ldsm4t(&bh[g * 4], bOffH + off);
                ldsm4t(&bl[g * 4], bOffL + off);
            }
#pragma unroll
            for (int t = 0; t < 4; t++) {
                int p = (t >> 1) * 4 + (t & 1) * 2;
                mma_bf16(acc[t], ah[0], ah[1], ah[2], ah[3], bh[p], bh[p + 1]);
                mma_bf16(acc[t], ah[0], ah[1], ah[2], ah[3], bl[p], bl[p + 1]);
                mma_bf16(acc[t], al[0], al[1], al[2], al[3], bh[p], bh[p + 1]);
            }
        }
        __syncthreads();
    }
    const int r0 = rb + wm * 16 + gid;
#pragma unroll
    for (int t = 0; t < 4; t++) {
        int c = cb + wn * 32 + t * 8 + tig * 2;
        out[(size_t)(r0    ) * H_DIM + c + 0] = acc[t][0];
        out[(size_t)(r0    ) * H_DIM + c + 1] = acc[t][1];
        out[(size_t)(r0 + 8) * H_DIM + c + 0] = acc[t][2];
        out[(size_t)(r0 + 8) * H_DIM + c + 1] = acc[t][3];
    }
}

// ------- routed gate_up: M=128 dual-A-tile, fp32 W inline conversion -------
__global__ __launch_bounds__(256) void routed_gateup_tc(
    const float* __restrict__ Wall /*[E,H,1024] fp32*/)
{
    const int e = blockIdx.z;
    const int cnt = g_counts[e];
    const int r0b = blockIdx.y * 128;
    if (r0b >= cnt) return;

    __shared__ __align__(16) __nv_bfloat16 sAh[128 * SA], sAl[128 * SA];
    __shared__ __align__(16) __nv_bfloat16 sGh[KC * SB], sGl[KC * SB];
    __shared__ __align__(16) __nv_bfloat16 sUh[KC * SB], sUl[KC * SB];

    const int tid = threadIdx.x, lane = tid & 31, wid = tid >> 5;
    const int gid = lane >> 2, tig = lane & 3;
    const int wm = wid & 3, wn = wid >> 2;
    const int cb = blockIdx.x * 64;

    const int ar = tid >> 2, ac8 = (tid & 3) * 8;
    const int bk = tid >> 3, bn8 = (tid & 7) * 8;

    int tok = 0, tok2 = 0;
    {
        int r = r0b + ar;
        if (r < cnt) tok = g_list[e * CAP + r] / TOPK;
        int r2 = r0b + 64 + ar;
        if (r2 < cnt) tok2 = g_list[e * CAP + r2] / TOPK;
    }
    const __nv_bfloat16* aH  = g_xs_h + (size_t)tok  * H_DIM + ac8;
    const __nv_bfloat16* aL  = g_xs_l + (size_t)tok  * H_DIM + ac8;
    const __nv_bfloat16* aH2 = g_xs_h + (size_t)tok2 * H_DIM + ac8;
    const __nv_bfloat16* aL2 = g_xs_l + (size_t)tok2 * H_DIM + ac8;
    const float* gW = Wall + (size_t)e * H_DIM * GUP_COLS + (size_t)bk * GUP_COLS + cb + bn8;
    const float* uW = gW + I_DIM;

    const uint32_t aBase = (uint32_t)((((wm * 16 + (lane & 15)) * SA) + (lane >> 4) * 8) * 2);
    uint32_t aOffH = (uint32_t)__cvta_generic_to_shared(sAh) + aBase;
    uint32_t aOffL = (uint32_t)__cvta_generic_to_shared(sAl) + aBase;
    const uint32_t aT2 = (uint32_t)(64 * SA * 2);
    const int mB = lane >> 3;
    const uint32_t bBase = (uint32_t)(((((mB & 1) * 8 + (lane & 7)) * SB) + wn * 32 + (mB >> 1) * 8) * 2);
    uint32_t gOffH = (uint32_t)__cvta_generic_to_shared(sGh) + bBase;
    uint32_t gOffL = (uint32_t)__cvta_generic_to_shared(sGl) + bBase;
    uint32_t uOffH = (uint32_t)__cvta_generic_to_shared(sUh) + bBase;
    uint32_t uOffL = (uint32_t)__cvta_generic_to_shared(sUl) + bBase;

    float accG[4][4] = {}, accU[4][4] = {};
    float accG2[4][4] = {}, accU2[4][4] = {};

    for (int k0 = 0; k0 < H_DIM; k0 += KC) {
        *(uint4*)&sAh[ar * SA + ac8]        = *(const uint4*)(aH  + k0);
        *(uint4*)&sAl[ar * SA + ac8]        = *(const uint4*)(aL  + k0);
        *(uint4*)&sAh[(64 + ar) * SA + ac8] = *(const uint4*)(aH2 + k0);
        *(uint4*)&sAl[(64 + ar) * SA + ac8] = *(const uint4*)(aL2 + k0);
        {
            const float* gp = gW + (size_t)k0 * GUP_COLS;
            const float* up = uW + (size_t)k0 * GUP_COLS;
            float4 v0 = *(const float4*)gp;
            float4 v1 = *(const float4*)(gp + 4);
            unsigned h01, l01, h23, l23;
            f2hl2(v0.x, v0.y, h01, l01); f2hl2(v0.z, v0.w, h23, l23);
            *(uint2*)&sGh[bk * SB + bn8] = make_uint2(h01, h23);
            *(uint2*)&sGl[bk * SB + bn8] = make_uint2(l01, l23);
            f2hl2(v1.x, v1.y, h01, l01); f2hl2(v1.z, v1.w, h23, l23);
            *(uint2*)&sGh[bk * SB + bn8 + 4] = make_uint2(h01, h23);
            *(uint2*)&sGl[bk * SB + bn8 + 4] = make_uint2(l01, l23);
            v0 = *(const float4*)up;
            v1 = *(const float4*)(up + 4);
            f2hl2(v0.x, v0.y, h01, l01); f2hl2(v0.z, v0.w, h23, l23);
            *(uint2*)&sUh[bk * SB + bn8] = make_uint2(h01, h23);
            *(uint2*)&sUl[bk * SB + bn8] = make_uint2(l01, l23);
            f2hl2(v1.x, v1.y, h01, l01); f2hl2(v1.z, v1.w, h23, l23);
            *(uint2*)&sUh[bk * SB + bn8 + 4] = make_uint2(h01, h23);
            *(uint2*)&sUl[bk * SB + bn8 + 4] = make_uint2(l01, l23);
        }
        __syncthreads();
#pragma unroll
        for (int s = 0; s < 2; s++) {
            unsigned ah[4], al[4], ah2[4], al2[4];
            ldsm4(ah,  aOffH + s * 32);
            ldsm4(al,  aOffL + s * 32);
            ldsm4(ah2, aOffH + aT2 + s * 32);
            ldsm4(al2, aOffL + aT2 + s * 32);
            unsigned gh[8], gl[8], uh[8], ul[8];
#pragma unroll
            for (int g = 0; g < 2; g++) {
                uint32_t off = (uint32_t)(s * 16 * SB) * 2 + g * 32;
                ldsm4t(&gh[g * 4], gOffH + off);
                ldsm4t(&gl[g * 4], gOffL + off);
                ldsm4t(&uh[g * 4], uOffH + off);
                ldsm4t(&ul[g * 4], uOffL + off);
            }
#pragma unroll
            for (int t = 0; t < 4; t++) {
                int p = (t >> 1) * 4 + (t & 1) * 2;
                mma_bf16(accG[t],  ah[0],  ah[1],  ah[2],  ah[3],  gh[p], gh[p + 1]);
                mma_bf16(accG[t],  ah[0],  ah[1],  ah[2],  ah[3],  gl[p], gl[p + 1]);
                mma_bf16(accG[t],  al[0],  al[1],  al[2],  al[3],  gh[p], gh[p + 1]);
                mma_bf16(accU[t],  ah[0],  ah[1],  ah[2],  ah[3],  uh[p], uh[p + 1]);
                mma_bf16(accU[t],  ah[0],  ah[1],  ah[2],  ah[3],  ul[p], ul[p + 1]);
                mma_bf16(accU[t],  al[0],  al[1],  al[2],  al[3],  uh[p], uh[p + 1]);
                mma_bf16(accG2[t], ah2[0], ah2[1], ah2[2], ah2[3], gh[p], gh[p + 1]);
                mma_bf16(accG2[t], ah2[0], ah2[1], ah2[2], ah2[3], gl[p], gl[p + 1]);
                mma_bf16(accG2[t], al2[0], al2[1], al2[2], al2[3], gh[p], gh[p + 1]);
                mma_bf16(accU2[t], ah2[0], ah2[1], ah2[2], ah2[3], uh[p], uh[p + 1]);
                mma_bf16(accU2[t], ah2[0], ah2[1], ah2[2], ah2[3], ul[p], ul[p + 1]);
                mma_bf16(accU2[t], al2[0], al2[1], al2[2], al2[3], uh[p], uh[p + 1]);
            }
        }
        __syncthreads();
    }
    const int rw = wm * 16 + gid;
#pragma unroll
    for (int t = 0; t < 4; t++) {
        int c = cb + wn * 32 + t * 8 + tig * 2;
#pragma unroll
        for (int i = 0; i < 2; i++) {
            int r = r0b + rw + i * 8;
            if (r < cnt) {
                float g0 = accG[t][i * 2], u0 = accU[t][i * 2];
                float g1 = accG[t][i * 2 + 1], u1 = accU[t][i * 2 + 1];
                float a0 = (g0 / (1.f + expf(-g0))) * u0;
                float a1 = (g1 / (1.f + expf(-g1))) * u1;
                unsigned h, l;
                f2hl2(a0, a1, h, l);
                *(unsigned*)&g_actr_h[((size_t)e * CAP + r) * I_DIM + c] = h;
                *(unsigned*)&g_actr_l[((size_t)e * CAP + r) * I_DIM + c] = l;
            }
            int r2 = r0b + 64 + rw + i * 8;
            if (r2 < cnt) {
                float g0 = accG2[t][i * 2], u0 = accU2[t][i * 2];
                float g1 = accG2[t][i * 2 + 1], u1 = accU2[t][i * 2 + 1];
                float a0 = (g0 / (1.f + expf(-g0))) * u0;
                float a1 = (g1 / (1.f + expf(-g1))) * u1;
                unsigned h, l;
                f2hl2(a0, a1, h, l);
                *(unsigned*)&g_actr_h[((size_t)e * CAP + r2) * I_DIM + c] = h;
                *(unsigned*)&g_actr_l[((size_t)e * CAP + r2) * I_DIM + c] = l;
            }
        }
    }
}

// ------- routed down: M=128 dual-A-tile, fp32 W inline conversion ----------
__global__ __launch_bounds__(256) void routed_down_tc(
    const float* __restrict__ Wall /*[E,512,1024] fp32*/)
{
    const int e = blockIdx.z;
    const int cnt = g_counts[e];
    const int r0b = blockIdx.y * 128;
    if (r0b >= cnt) return;

    __shared__ __align__(16) __nv_bfloat16 sAh[128 * SA], sAl[128 * SA];
    __shared__ __align__(16) __nv_bfloat16 sBh[KC * SB], sBl[KC * SB];

    const int tid = threadIdx.x, lane = tid & 31, wid = tid >> 5;
    const int gid = lane >> 2, tig = lane & 3;
    const int wm = wid & 3, wn = wid >> 2;
    const int cb = blockIdx.x * 64;

    const int ar = tid >> 2, ac8 = (tid & 3) * 8;
    const int bk = tid >> 3, bn8 = (tid & 7) * 8;

    const __nv_bfloat16* aH  = g_actr_h + ((size_t)e * CAP + (r0b + ar)) * I_DIM + ac8;
    const __nv_bfloat16* aL  = g_actr_l + ((size_t)e * CAP + (r0b + ar)) * I_DIM + ac8;
    const __nv_bfloat16* aH2 = aH + (size_t)64 * I_DIM;
    const __nv_bfloat16* aL2 = aL + (size_t)64 * I_DIM;
    const float* bW = Wall + (size_t)e * I_DIM * H_DIM + (size_t)bk * H_DIM + cb + bn8;

    const uint32_t aBase = (uint32_t)((((wm * 16 + (lane & 15)) * SA) + (lane >> 4) * 8) * 2);
    uint32_t aOffH = (uint32_t)__cvta_generic_to_shared(sAh) + aBase;
    uint32_t aOffL = (uint32_t)__cvta_generic_to_shared(sAl) + aBase;
    const uint32_t aT2 = (uint32_t)(64 * SA * 2);
    const int mB = lane >> 3;
    const uint32_t bBase = (uint32_t)(((((mB & 1) * 8 + (lane & 7)) * SB) + wn * 32 + (mB >> 1) * 8) * 2);
    uint32_t bOffH = (uint32_t)__cvta_generic_to_shared(sBh) + bBase;
    uint32_t bOffL = (uint32_t)__cvta_generic_to_shared(sBl) + bBase;

    float acc[4][4] = {}, acc2[4][4] = {};

    for (int k0 = 0; k0 < I_DIM; k0 += KC) {
        *(uint4*)&sAh[ar * SA + ac8]        = *(const uint4*)(aH  + k0);
        *(uint4*)&sAl[ar * SA + ac8]        = *(const uint4*)(aL  + k0);
        *(uint4*)&sAh[(64 + ar) * SA + ac8] = *(const uint4*)(aH2 + k0);
        *(uint4*)&sAl[(64 + ar) * SA + ac8] = *(const uint4*)(aL2 + k0);
        {
            const float* bp = bW + (size_t)k0 * H_DIM;
            float4 v0 = *(const float4*)bp;
            float4 v1 = *(const float4*)(bp + 4);
            unsigned h01, l01, h23, l23;
            f2hl2(v0.x, v0.y, h01, l01); f2hl2(v0.z, v0.w, h23, l23);
            *(uint2*)&sBh[bk * SB + bn8] = make_uint2(h01, h23);
            *(uint2*)&sBl[bk * SB + bn8] = make_uint2(l01, l23);
            f2hl2(v1.x, v1.y, h01, l01); f2hl2(v1.z, v1.w, h23, l23);
            *(uint2*)&sBh[bk * SB + bn8 + 4] = make_uint2(h01, h23);
            *(uint2*)&sBl[bk * SB + bn8 + 4] = make_uint2(l01, l23);
        }
        __syncthreads();
#pragma unroll
        for (int s = 0; s < 2; s++) {
            unsigned ah[4], al[4], ah2[4], al2[4];
            ldsm4(ah,  aOffH + s * 32);
            ldsm4(al,  aOffL + s * 32);
            ldsm4(ah2, aOffH + aT2 + s * 32);
            ldsm4(al2, aOffL + aT2 + s * 32);
            unsigned bh[8], bl[8];
#pragma unroll
            for (int g = 0; g < 2; g++) {
                uint32_t off = (uint32_t)(s * 16 * SB) * 2 + g * 32;
                ldsm4t(&bh[g * 4], bOffH + off);
                ldsm4t(&bl[g * 4], bOffL + off);
            }
#pragma unroll
            for (int t = 0; t < 4; t++) {
                int p = (t >> 1) * 4 + (t & 1) * 2;
                mma_bf16(acc[t],  ah[0],  ah[1],  ah[2],  ah[3],  bh[p], bh[p + 1]);
                mma_bf16(acc[t],  ah[0],  ah[1],  ah[2],  ah[3],  bl[p], bl[p + 1]);
                mma_bf16(acc[t],  al[0],  al[1],  al[2],  al[3],  bh[p], bh[p + 1]);
                mma_bf16(acc2[t], ah2[0], ah2[1], ah2[2], ah2[3], bh[p], bh[p + 1]);
                mma_bf16(acc2[t], ah2[0], ah2[1], ah2[2], ah2[3], bl[p], bl[p + 1]);
                mma_bf16(acc2[t], al2[0], al2[1], al2[2], al2[3], bh[p], bh[p + 1]);
            }
        }
        __syncthreads();
    }
    const int rw = wm * 16 + gid;
#pragma unroll
    for (int t = 0; t < 4; t++) {
        int c = cb + wn * 32 + t * 8 + tig * 2;
#pragma unroll
        for (int i = 0; i < 2; i++) {
            int r = r0b + rw + i * 8;
            if (r < cnt) {
                int a = g_list[e * CAP + r];
                g_ybuf[(size_t)a * H_DIM + c + 0] = acc[t][i * 2 + 0];
                g_ybuf[(size_t)a * H_DIM + c + 1] = acc[t][i * 2 + 1];
            }
            int r2 = r0b + 64 + rw + i * 8;
            if (r2 < cnt) {
                int a = g_list[e * CAP + r2];
                g_ybuf[(size_t)a * H_DIM + c + 0] = acc2[t][i * 2 + 0];
                g_ybuf[(size_t)a * H_DIM + c + 1] = acc2[t][i * 2 + 1];
            }
        }
    }
}

// ------------------------------- combine -----------------------------------
__global__ __launch_bounds__(256) void combine_kernel(float* __restrict__ out)
{
    const int t = blockIdx.x;
    const int h4 = threadIdx.x * 4;
    float4 o = *(float4*)(out + (size_t)t * H_DIM + h4);
    float r0 = o.x, r1 = o.y, r2 = o.z, r3 = o.w;
#pragma unroll
    for (int k = 0; k < TOPK; k++) {
        int a = t * TOPK + k;
        if (g_keep[a]) {
            float wv = g_w[a] * SCALE_F;
            float4 y = *(const float4*)(g_ybuf + (size_t)a * H_DIM + h4);
            r0 += wv * y.x; r1 += wv * y.y; r2 += wv * y.z; r3 += wv * y.w;
        }
    }
    *(float4*)(out + (size_t)t * H_DIM + h4) = make_float4(r0, r1, r2, r3);
}

// ------------------------------- launcher ----------------------------------
extern "C" void kernel_launch(void* const* d_in, const int* in_sizes, int n_in,
                              void* d_out, int out_size)
{
    const float* x          = (const float*)d_in[0];
    const float* gate_w     = (const float*)d_in[1];
    const float* e_bias     = (const float*)d_in[2];
    const float* w_gate_up  = (const float*)d_in[3];
    const float* w_down     = (const float*)d_in[4];
    const float* ws_gate_up = (const float*)d_in[5];
    const float* ws_down    = (const float*)d_in[6];
    float* out = (float*)d_out;

    __nv_bfloat16 *xs_h, *xs_l, *wsgu_h, *wsgu_l, *wsd_h, *wsd_l;
    cudaGetSymbolAddress((void**)&xs_h, g_xs_h);
    cudaGetSymbolAddress((void**)&xs_l, g_xs_l);
    cudaGetSymbolAddress((void**)&wsgu_h, g_wsgu_h);
    cudaGetSymbolAddress((void**)&wsgu_l, g_wsgu_l);
    cudaGetSymbolAddress((void**)&wsd_h, g_wsd_h);
    cudaGetSymbolAddress((void**)&wsd_l, g_wsd_l);

    auto split = [](const float* s, __nv_bfloat16* h, __nv_bfloat16* l, size_t n) {
        int n4 = (int)(n / 4);
        split_kernel<<<(n4 + 255) / 256, 256>>>((const float4*)s, (uint2*)h, (uint2*)l, n4);
    };

    split(x,          xs_h,   xs_l,   (size_t)T_TOK * H_DIM);
    split(ws_gate_up, wsgu_h, wsgu_l, (size_t)H_DIM * SH_GUP);
    split(ws_down,    wsd_h,  wsd_l,  (size_t)SH_ACT * H_DIM);

    router_kernel<<<T_TOK / 4, 256>>>(x, gate_w, e_bias);
    dispatch_kernel<<<E_EXP, 256>>>();

    shared_gateup_tc<<<dim3(SH_ACT / 64, T_TOK / 64), 256>>>();
    shared_down_tc<<<dim3(H_DIM / 64, T_TOK / 64), 256>>>(out);
    routed_gateup_tc<<<dim3(I_DIM / 64, CAP / 128, E_EXP), 256>>>(w_gate_up);
    routed_down_tc<<<dim3(H_DIM / 64, CAP / 128, E_EXP), 256>>>(w_down);
    combine_kernel<<<T_TOK, 256>>>(out);
}

// round 11
// speedup vs baseline: 2.2637x; 1.2340x over previous
#include <cuda_runtime.h>
#include <cuda_bf16.h>
#include <cstdint>
#include <math.h>

// ---------------------------------------------------------------------------
// DeepseekV2 MoE.
//  - x + shared weights: one-time hi/lo bf16 plane splits.
//  - GEMMs: ldmatrix + m16n8k16 3-term hi/lo MMA, register-prefetch pipelined
//    mainloops (global loads for chunk k+1 issued before MMA of chunk k).
//  - Routed GEMMs: M=128 dual-A-tile, fp32 weights converted inline.
//  - Router: 4 tokens/block, 8 H-slices, warp-shuffle grouped top-k.
// ---------------------------------------------------------------------------

#define T_TOK   1024
#define H_DIM   1024
#define E_EXP   64
#define I_DIM   512
#define TOPK    6
#define NGROUP  8
#define TKG     3
#define CAP     256
#define A_TOT   (T_TOK * TOPK)
#define SCALE_F 2.5f
#define GUP_COLS (2 * I_DIM)
#define SH_ACT   1024
#define SH_GUP   2048

#define KC 32
#define SA 40
#define SB 72

// ------------------------------- scratch -----------------------------------
__device__ float g_w[A_TOT];
__device__ int   g_eidx[A_TOT];
__device__ int   g_counts[E_EXP];
__device__ int   g_list[E_EXP * CAP];
__device__ int   g_keep[A_TOT];

__device__ __nv_bfloat16 g_xs_h[T_TOK * H_DIM];
__device__ __nv_bfloat16 g_xs_l[T_TOK * H_DIM];
__device__ __nv_bfloat16 g_wsgu_h[H_DIM * SH_GUP];
__device__ __nv_bfloat16 g_wsgu_l[H_DIM * SH_GUP];
__device__ __nv_bfloat16 g_wsd_h[SH_ACT * H_DIM];
__device__ __nv_bfloat16 g_wsd_l[SH_ACT * H_DIM];
__device__ __nv_bfloat16 g_acts_h[T_TOK * SH_ACT];
__device__ __nv_bfloat16 g_acts_l[T_TOK * SH_ACT];
__device__ __nv_bfloat16 g_actr_h[(size_t)E_EXP * CAP * I_DIM];
__device__ __nv_bfloat16 g_actr_l[(size_t)E_EXP * CAP * I_DIM];
__device__ float g_ybuf[(size_t)A_TOT * H_DIM];

// ------------------------------- helpers -----------------------------------
__device__ __forceinline__ unsigned pack2(__nv_bfloat16 a, __nv_bfloat16 b) {
    __nv_bfloat162 t = __halves2bfloat162(a, b);
    return *(unsigned*)&t;
}

__device__ __forceinline__ void f2hl2(float x, float y, unsigned& h, unsigned& l) {
    __nv_bfloat16 h0 = __float2bfloat16(x), h1 = __float2bfloat16(y);
    __nv_bfloat16 l0 = __float2bfloat16(x - __bfloat162float(h0));
    __nv_bfloat16 l1 = __float2bfloat16(y - __bfloat162float(h1));
    h = pack2(h0, h1);
    l = pack2(l0, l1);
}

__device__ __forceinline__ void mma_bf16(float c[4],
    unsigned a0, unsigned a1, unsigned a2, unsigned a3,
    unsigned b0, unsigned b1)
{
    asm volatile(
        "mma.sync.aligned.m16n8k16.row.col.f32.bf16.bf16.f32 "
        "{%0,%1,%2,%3}, {%4,%5,%6,%7}, {%8,%9}, {%0,%1,%2,%3};"
        : "+f"(c[0]), "+f"(c[1]), "+f"(c[2]), "+f"(c[3])
        : "r"(a0), "r"(a1), "r"(a2), "r"(a3), "r"(b0), "r"(b1));
}

__device__ __forceinline__ void ldsm4(unsigned* r, uint32_t addr) {
    asm volatile("ldmatrix.sync.aligned.m8n8.x4.shared.b16 {%0,%1,%2,%3}, [%4];"
        : "=r"(r[0]), "=r"(r[1]), "=r"(r[2]), "=r"(r[3]) : "r"(addr));
}
__device__ __forceinline__ void ldsm4t(unsigned* r, uint32_t addr) {
    asm volatile("ldmatrix.sync.aligned.m8n8.x4.trans.shared.b16 {%0,%1,%2,%3}, [%4];"
        : "=r"(r[0]), "=r"(r[1]), "=r"(r[2]), "=r"(r[3]) : "r"(addr));
}

// ------------------------------- split -------------------------------------
__global__ __launch_bounds__(256) void split_kernel(
    const float4* __restrict__ src, uint2* __restrict__ hi, uint2* __restrict__ lo, int n4)
{
    int i = blockIdx.x * 256 + threadIdx.x;
    if (i >= n4) return;
    float4 v = src[i];
    unsigned h01, l01, h23, l23;
    f2hl2(v.x, v.y, h01, l01);
    f2hl2(v.z, v.w, h23, l23);
    hi[i] = make_uint2(h01, h23);
    lo[i] = make_uint2(l01, l23);
}

// ----------- router: 4 tokens/block, 512 thr, 8 H-slices -------------------
__global__ __launch_bounds__(512) void router_kernel(
    const float* __restrict__ x, const float* __restrict__ gw,
    const float* __restrict__ bias)
{
    __shared__ float xs[4][H_DIM];       // 16 KB
    __shared__ float part[4][8][E_EXP];  // 8 KB  [token][slice][expert]
    const int tid = threadIdx.x;
    const unsigned FULL = 0xffffffffu;

    for (int i = tid; i < 4 * (H_DIM / 4); i += 512) {
        int row = i >> 8, c4 = (i & 255) * 4;
        *(float4*)&xs[row][c4] = *(const float4*)(x + (size_t)(blockIdx.x * 4 + row) * H_DIM + c4);
    }
    __syncthreads();

    // logits partials: thread (slice = tid>>6 in [0,8), expert = tid&63)
    {
        const int e = tid & 63, sl = tid >> 6;
        const float* gp = gw + e;
        float a0 = 0.f, a1 = 0.f, a2 = 0.f, a3 = 0.f;
        const int h0 = sl * 128;
#pragma unroll 8
        for (int h = h0; h < h0 + 128; h++) {
            float gv = gp[h * E_EXP];
            a0 += xs[0][h] * gv;
            a1 += xs[1][h] * gv;
            a2 += xs[2][h] * gv;
            a3 += xs[3][h] * gv;
        }
        part[0][sl][e] = a0;
        part[1][sl][e] = a1;
        part[2][sl][e] = a2;
        part[3][sl][e] = a3;
    }
    __syncthreads();

    const int warp = tid >> 5, lane = tid & 31;
    if (warp >= 4) return;
    const int t = blockIdx.x * 4 + warp;

    float lg0 = 0.f, lg1 = 0.f;
#pragma unroll
    for (int sl = 0; sl < 8; sl++) {
        lg0 += part[warp][sl][lane];
        lg1 += part[warp][sl][lane + 32];
    }
    float sc0 = 1.f / (1.f + expf(-lg0));
    float sc1 = 1.f / (1.f + expf(-lg1));
    float s0 = sc0 + bias[lane];
    float s1 = sc1 + bias[lane + 32];

    float m1a = s0, m2a = -INFINITY;
    float m1b = s1, m2b = -INFINITY;
#pragma unroll
    for (int off = 4; off >= 1; off >>= 1) {
        float o1 = __shfl_xor_sync(FULL, m1a, off);
        float o2 = __shfl_xor_sync(FULL, m2a, off);
        if (o1 > m1a) { m2a = fmaxf(m1a, o2); m1a = o1; }
        else          { m2a = fmaxf(m2a, o1); }
        o1 = __shfl_xor_sync(FULL, m1b, off);
        o2 = __shfl_xor_sync(FULL, m2b, off);
        if (o1 > m1b) { m2b = fmaxf(m1b, o2); m1b = o1; }
        else          { m2b = fmaxf(m2b, o1); }
    }
    float gsv0 = m1a + m2a;
    float gsv1 = m1b + m2b;

    float gs[NGROUP];
#pragma unroll
    for (int g = 0; g < 4; g++) {
        gs[g]     = __shfl_sync(FULL, gsv0, g * 8);
        gs[4 + g] = __shfl_sync(FULL, gsv1, g * 8);
    }
    bool gsel[NGROUP];
#pragma unroll
    for (int g = 0; g < NGROUP; g++) gsel[g] = false;
#pragma unroll
    for (int it = 0; it < TKG; it++) {
        int bi = -1; float bv = -INFINITY;
#pragma unroll
        for (int g = 0; g < NGROUP; g++)
            if (!gsel[g] && gs[g] > bv) { bv = gs[g]; bi = g; }
        gsel[bi] = true;
    }

    float t0 = gsel[lane >> 3]       ? s0 : -INFINITY;
    float t1 = gsel[(lane >> 3) + 4] ? s1 : -INFINITY;

    int   idxk[TOPK];
    float wvk[TOPK];
    float wsum = 0.f;
#pragma unroll
    for (int k = 0; k < TOPK; k++) {
        float bv; int be;
        if (t0 >= t1) { bv = t0; be = lane; }
        else          { bv = t1; be = lane + 32; }
#pragma unroll
        for (int off = 16; off >= 1; off >>= 1) {
            float ov = __shfl_xor_sync(FULL, bv, off);
            int   oi = __shfl_xor_sync(FULL, be, off);
            if (ov > bv || (ov == bv && oi < be)) { bv = ov; be = oi; }
        }
        float scw = __shfl_sync(FULL, (be & 32) ? sc1 : sc0, be & 31);
        idxk[k] = be;
        wvk[k]  = scw;
        wsum   += scw;
        if (lane == (be & 31)) {
            if (be & 32) t1 = -INFINITY; else t0 = -INFINITY;
        }
    }
    if (lane == 0) {
        float inv = 1.f / wsum;
#pragma unroll
        for (int k = 0; k < TOPK; k++) {
            g_w[t * TOPK + k]    = wvk[k] * inv;
            g_eidx[t * TOPK + k] = idxk[k];
        }
    }
}

// ------------------------------ dispatch -----------------------------------
__global__ __launch_bounds__(256) void dispatch_kernel()
{
    const int e = blockIdx.x, tid = threadIdx.x;
    const int lane = tid & 31, wid = tid >> 5;
    __shared__ int warp_tot[8];
    int base = 0;
    for (int chunk = 0; chunk < A_TOT; chunk += 256) {
        int a = chunk + tid;
        int m = (a < A_TOT && g_eidx[a] == e) ? 1 : 0;
        unsigned bal = __ballot_sync(0xffffffffu, m);
        if (lane == 0) warp_tot[wid] = __popc(bal);
        __syncthreads();
        int woff = 0, tot = 0;
#pragma unroll
        for (int i = 0; i < 8; i++) { if (i < wid) woff += warp_tot[i]; tot += warp_tot[i]; }
        if (m) {
            int pos = base + woff + __popc(bal & ((1u << lane) - 1u));
            if (pos < CAP) g_list[e * CAP + pos] = a;
            g_keep[a] = (pos < CAP) ? 1 : 0;
        }
        base += tot;
        __syncthreads();
    }
    if (tid == 0) g_counts[e] = base < CAP ? base : CAP;
}

// ===========================================================================
// Shared GEMMs: 64x64 tile, 256 thr = 8 warps (4M x 2N), warp = 16x32.
// Pipelined: global loads for chunk k+1 issued before MMA of chunk k.
// ===========================================================================

__global__ __launch_bounds__(256) void shared_gateup_tc()
{
    __shared__ __align__(16) __nv_bfloat16 sAh[64 * SA], sAl[64 * SA];
    __shared__ __align__(16) __nv_bfloat16 sGh[KC * SB], sGl[KC * SB];
    __shared__ __align__(16) __nv_bfloat16 sUh[KC * SB], sUl[KC * SB];

    const int tid = threadIdx.x, lane = tid & 31, wid = tid >> 5;
    const int gid = lane >> 2, tig = lane & 3;
    const int wm = wid & 3, wn = wid >> 2;
    const int rb = blockIdx.y * 64, cb = blockIdx.x * 64;

    const int ar = tid >> 2, ac8 = (tid & 3) * 8;
    const int bk = tid >> 3, bn8 = (tid & 7) * 8;

    const __nv_bfloat16* aH = g_xs_h + (size_t)(rb + ar) * H_DIM + ac8;
    const __nv_bfloat16* aL = g_xs_l + (size_t)(rb + ar) * H_DIM + ac8;
    const __nv_bfloat16* gH = g_wsgu_h + (size_t)bk * SH_GUP + cb + bn8;
    const __nv_bfloat16* gL = g_wsgu_l + (size_t)bk * SH_GUP + cb + bn8;
    const __nv_bfloat16* uH = gH + SH_ACT;
    const __nv_bfloat16* uL = gL + SH_ACT;

    const uint32_t aBase = (uint32_t)((((wm * 16 + (lane & 15)) * SA) + (lane >> 4) * 8) * 2);
    uint32_t aOffH = (uint32_t)__cvta_generic_to_shared(sAh) + aBase;
    uint32_t aOffL = (uint32_t)__cvta_generic_to_shared(sAl) + aBase;
    const int mB = lane >> 3;
    const uint32_t bBase = (uint32_t)(((((mB & 1) * 8 + (lane & 7)) * SB) + wn * 32 + (mB >> 1) * 8) * 2);
    uint32_t gOffH = (uint32_t)__cvta_generic_to_shared(sGh) + bBase;
    uint32_t gOffL = (uint32_t)__cvta_generic_to_shared(sGl) + bBase;
    uint32_t uOffH = (uint32_t)__cvta_generic_to_shared(sUh) + bBase;
    uint32_t uOffL = (uint32_t)__cvta_generic_to_shared(sUl) + bBase;

    float accG[4][4] = {}, accU[4][4] = {};

    uint4 pA0 = *(const uint4*)(aH);
    uint4 pA1 = *(const uint4*)(aL);
    uint4 pG0 = *(const uint4*)(gH);
    uint4 pG1 = *(const uint4*)(gL);
    uint4 pU0 = *(const uint4*)(uH);
    uint4 pU1 = *(const uint4*)(uL);

    for (int k0 = 0; k0 < H_DIM; k0 += KC) {
        *(uint4*)&sAh[ar * SA + ac8] = pA0;
        *(uint4*)&sAl[ar * SA + ac8] = pA1;
        *(uint4*)&sGh[bk * SB + bn8] = pG0;
        *(uint4*)&sGl[bk * SB + bn8] = pG1;
        *(uint4*)&sUh[bk * SB + bn8] = pU0;
        *(uint4*)&sUl[bk * SB + bn8] = pU1;
        __syncthreads();
        if (k0 + KC < H_DIM) {
            pA0 = *(const uint4*)(aH + k0 + KC);
            pA1 = *(const uint4*)(aL + k0 + KC);
            pG0 = *(const uint4*)(gH + (size_t)(k0 + KC) * SH_GUP);
            pG1 = *(const uint4*)(gL + (size_t)(k0 + KC) * SH_GUP);
            pU0 = *(const uint4*)(uH + (size_t)(k0 + KC) * SH_GUP);
            pU1 = *(const uint4*)(uL + (size_t)(k0 + KC) * SH_GUP);
        }
#pragma unroll
        for (int s = 0; s < 2; s++) {
            unsigned ah[4], al[4];
            ldsm4(ah, aOffH + s * 32);
            ldsm4(al, aOffL + s * 32);
            unsigned gh[8], gl[8], uh[8], ul[8];
#pragma unroll
            for (int g = 0; g < 2; g++) {
                uint32_t off = (uint32_t)(s * 16 * SB) * 2 + g * 32;
                ldsm4t(&gh[g * 4], gOffH + off);
                ldsm4t(&gl[g * 4], gOffL + off);
                ldsm4t(&uh[g * 4], uOffH + off);
                ldsm4t(&ul[g * 4], uOffL + off);
            }
#pragma unroll
            for (int t = 0; t < 4; t++) {
                int p = (t >> 1) * 4 + (t & 1) * 2;
                mma_bf16(accG[t], ah[0], ah[1], ah[2], ah[3], gh[p], gh[p + 1]);
                mma_bf16(accG[t], ah[0], ah[1], ah[2], ah[3], gl[p], gl[p + 1]);
                mma_bf16(accG[t], al[0], al[1], al[2], al[3], gh[p], gh[p + 1]);
                mma_bf16(accU[t], ah[0], ah[1], ah[2], ah[3], uh[p], uh[p + 1]);
                mma_bf16(accU[t], ah[0], ah[1], ah[2], ah[3], ul[p], ul[p + 1]);
                mma_bf16(accU[t], al[0], al[1], al[2], al[3], uh[p], uh[p + 1]);
            }
        }
        __syncthreads();
    }
    const int r0 = rb + wm * 16 + gid;
#pragma unroll
    for (int t = 0; t < 4; t++) {
        int c = cb + wn * 32 + t * 8 + tig * 2;
#pragma unroll
        for (int i = 0; i < 2; i++) {
            int r = r0 + i * 8;
            float g0 = accG[t][i * 2], u0 = accU[t][i * 2];
            float g1 = accG[t][i * 2 + 1], u1 = accU[t][i * 2 + 1];
            float a0 = (g0 / (1.f + expf(-g0))) * u0;
            float a1 = (g1 / (1.f + expf(-g1))) * u1;
            unsigned h, l;
            f2hl2(a0, a1, h, l);
            *(unsigned*)&g_acts_h[(size_t)r * SH_ACT + c] = h;
            *(unsigned*)&g_acts_l[(size_t)r * SH_ACT + c] = l;
        }
    }
}

__global__ __launch_bounds__(256) void shared_down_tc(float* __restrict__ out)
{
    __shared__ __align__(16) __nv_bfloat16 sAh[64 * SA], sAl[64 * SA];
    __shared__ __align__(16) __nv_bfloat16 sBh[KC * SB], sBl[KC * SB];

    const int tid = threadIdx.x, lane = tid & 31, wid = tid >> 5;
    const int gid = lane >> 2, tig = lane & 3;
    const int wm = wid & 3, wn = wid >> 2;
    const int rb = blockIdx.y * 64, cb = blockIdx.x * 64;

    const int ar = tid >> 2, ac8 = (tid & 3) * 8;
    const int bk = tid >> 3, bn8 = (tid & 7) * 8;

    const __nv_bfloat16* aH = g_acts_h + (size_t)(rb + ar) * SH_ACT + ac8;
    const __nv_bfloat16* aL = g_acts_l + (size_t)(rb + ar) * SH_ACT + ac8;
    const __nv_bfloat16* bH = g_wsd_h + (size_t)bk * H_DIM + cb + bn8;
    const __nv_bfloat16* bL = g_wsd_l + (size_t)bk * H_DIM + cb + bn8;

    const uint32_t aBase = (uint32_t)((((wm * 16 + (lane & 15)) * SA) + (lane >> 4) * 8) * 2);
    uint32_t aOffH = (uint32_t)__cvta_generic_to_shared(sAh) + aBase;
    uint32_t aOffL = (uint32_t)__cvta_generic_to_shared(sAl) + aBase;
    const int mB = lane >> 3;
    const uint32_t bBase = (uint32_t)(((((mB & 1) * 8 + (lane & 7)) * SB) + wn * 32 + (mB >> 1) * 8) * 2);
    uint32_t bOffH = (uint32_t)__cvta_generic_to_shared(sBh) + bBase;
    uint32_t bOffL = (uint32_t)__cvta_generic_to_shared(sBl) + bBase;

    float acc[4][4] = {};

    uint4 pA0 = *(const uint4*)(aH);
    uint4 pA1 = *(const uint4*)(aL);
    uint4 pB0 = *(const uint4*)(bH);
    uint4 pB1 = *(const uint4*)(bL);

    for (int k0 = 0; k0 < SH_ACT; k0 += KC) {
        *(uint4*)&sAh[ar * SA + ac8] = pA0;
        *(uint4*)&sAl[ar * SA + ac8] = pA1;
        *(uint4*)&sBh[bk * SB + bn8] = pB0;
        *(uint4*)&sBl[bk * SB + bn8] = pB1;
        __syncthreads();
        if (k0 + KC < SH_ACT) {
            pA0 = *(const uint4*)(aH + k0 + KC);
            pA1 = *(const uint4*)(aL + k0 + KC);
            pB0 = *(const uint4*)(bH + (size_t)(k0 + KC) * H_DIM);
            pB1 = *(const uint4*)(bL + (size_t)(k0 + KC) * H_DIM);
        }
#pragma unroll
        for (int s = 0; s < 2; s++) {
            unsigned ah[4], al[4];
            ldsm4(ah, aOffH + s * 32);
            ldsm4(al, aOffL + s * 32);
            unsigned bh[8], bl[8];
#pragma unroll
            for (int g = 0; g < 2; g++) {
                uint32_t off = (uint32_t)(s * 16 * SB) * 2 + g * 32;
                ldsm4t(&bh[g * 4], bOffH + off);
                ldsm4t(&bl[g * 4], bOffL + off);
            }
#pragma unroll
            for (int t = 0; t < 4; t++) {
                int p = (t >> 1) * 4 + (t & 1) * 2;
                mma_bf16(acc[t], ah[0], ah[1], ah[2], ah[3], bh[p], bh[p + 1]);
                mma_bf16(acc[t], ah[0], ah[1], ah[2], ah[3], bl[p], bl[p + 1]);
                mma_bf16(acc[t], al[0], al[1], al[2], al[3], bh[p], bh[p + 1]);
            }
        }
        __syncthreads();
    }
    const int r0 = rb + wm * 16 + gid;
#pragma unroll
    for (int t = 0; t < 4; t++) {
        int c = cb + wn * 32 + t * 8 + tig * 2;
        out[(size_t)(r0    ) * H_DIM + c + 0] = acc[t][0];
        out[(size_t)(r0    ) * H_DIM + c + 1] = acc[t][1];
        out[(size_t)(r0 + 8) * H_DIM + c + 0] = acc[t][2];
        out[(size_t)(r0 + 8) * H_DIM + c + 1] = acc[t][3];
    }
}

// ------- routed gate_up: M=128 dual-A-tile, pipelined ----------------------
__global__ __launch_bounds__(256) void routed_gateup_tc(
    const float* __restrict__ Wall /*[E,H,1024] fp32*/)
{
    const int e = blockIdx.z;
    const int cnt = g_counts[e];
    const int r0b = blockIdx.y * 128;
    if (r0b >= cnt) return;

    __shared__ __align__(16) __nv_bfloat16 sAh[128 * SA], sAl[128 * SA];
    __shared__ __align__(16) __nv_bfloat16 sGh[KC * SB], sGl[KC * SB];
    __shared__ __align__(16) __nv_bfloat16 sUh[KC * SB], sUl[KC * SB];

    const int tid = threadIdx.x, lane = tid & 31, wid = tid >> 5;
    const int gid = lane >> 2, tig = lane & 3;
    const int wm = wid & 3, wn = wid >> 2;
    const int cb = blockIdx.x * 64;

    const int ar = tid >> 2, ac8 = (tid & 3) * 8;
    const int bk = tid >> 3, bn8 = (tid & 7) * 8;

    int tok = 0, tok2 = 0;
    {
        int r = r0b + ar;
        if (r < cnt) tok = g_list[e * CAP + r] / TOPK;
        int r2 = r0b + 64 + ar;
        if (r2 < cnt) tok2 = g_list[e * CAP + r2] / TOPK;
    }
    const __nv_bfloat16* aH  = g_xs_h + (size_t)tok  * H_DIM + ac8;
    const __nv_bfloat16* aL  = g_xs_l + (size_t)tok  * H_DIM + ac8;
    const __nv_bfloat16* aH2 = g_xs_h + (size_t)tok2 * H_DIM + ac8;
    const __nv_bfloat16* aL2 = g_xs_l + (size_t)tok2 * H_DIM + ac8;
    const float* gW = Wall + (size_t)e * H_DIM * GUP_COLS + (size_t)bk * GUP_COLS + cb + bn8;
    const float* uW = gW + I_DIM;

    const uint32_t aBase = (uint32_t)((((wm * 16 + (lane & 15)) * SA) + (lane >> 4) * 8) * 2);
    uint32_t aOffH = (uint32_t)__cvta_generic_to_shared(sAh) + aBase;
    uint32_t aOffL = (uint32_t)__cvta_generic_to_shared(sAl) + aBase;
    const uint32_t aT2 = (uint32_t)(64 * SA * 2);
    const int mB = lane >> 3;
    const uint32_t bBase = (uint32_t)(((((mB & 1) * 8 + (lane & 7)) * SB) + wn * 32 + (mB >> 1) * 8) * 2);
    uint32_t gOffH = (uint32_t)__cvta_generic_to_shared(sGh) + bBase;
    uint32_t gOffL = (uint32_t)__cvta_generic_to_shared(sGl) + bBase;
    uint32_t uOffH = (uint32_t)__cvta_generic_to_shared(sUh) + bBase;
    uint32_t uOffL = (uint32_t)__cvta_generic_to_shared(sUl) + bBase;

    float accG[4][4] = {}, accU[4][4] = {};
    float accG2[4][4] = {}, accU2[4][4] = {};

    uint4  pA0 = *(const uint4*)(aH);
    uint4  pA1 = *(const uint4*)(aL);
    uint4  pA2 = *(const uint4*)(aH2);
    uint4  pA3 = *(const uint4*)(aL2);
    float4 pg0 = *(const float4*)(gW);
    float4 pg1 = *(const float4*)(gW + 4);
    float4 pu0 = *(const float4*)(uW);
    float4 pu1 = *(const float4*)(uW + 4);

    for (int k0 = 0; k0 < H_DIM; k0 += KC) {
        *(uint4*)&sAh[ar * SA + ac8]        = pA0;
        *(uint4*)&sAl[ar * SA + ac8]        = pA1;
        *(uint4*)&sAh[(64 + ar) * SA + ac8] = pA2;
        *(uint4*)&sAl[(64 + ar) * SA + ac8] = pA3;
        {
            unsigned h01, l01, h23, l23;
            f2hl2(pg0.x, pg0.y, h01, l01); f2hl2(pg0.z, pg0.w, h23, l23);
            *(uint2*)&sGh[bk * SB + bn8] = make_uint2(h01, h23);
            *(uint2*)&sGl[bk * SB + bn8] = make_uint2(l01, l23);
            f2hl2(pg1.x, pg1.y, h01, l01); f2hl2(pg1.z, pg1.w, h23, l23);
            *(uint2*)&sGh[bk * SB + bn8 + 4] = make_uint2(h01, h23);
            *(uint2*)&sGl[bk * SB + bn8 + 4] = make_uint2(l01, l23);
            f2hl2(pu0.x, pu0.y, h01, l01); f2hl2(pu0.z, pu0.w, h23, l23);
            *(uint2*)&sUh[bk * SB + bn8] = make_uint2(h01, h23);
            *(uint2*)&sUl[bk * SB + bn8] = make_uint2(l01, l23);
            f2hl2(pu1.x, pu1.y, h01, l01); f2hl2(pu1.z, pu1.w, h23, l23);
            *(uint2*)&sUh[bk * SB + bn8 + 4] = make_uint2(h01, h23);
            *(uint2*)&sUl[bk * SB + bn8 + 4] = make_uint2(l01, l23);
        }
        __syncthreads();
        if (k0 + KC < H_DIM) {
            pA0 = *(const uint4*)(aH  + k0 + KC);
            pA1 = *(const uint4*)(aL  + k0 + KC);
            pA2 = *(const uint4*)(aH2 + k0 + KC);
            pA3 = *(const uint4*)(aL2 + k0 + KC);
            const float* gp = gW + (size_t)(k0 + KC) * GUP_COLS;
            const float* up = uW + (size_t)(k0 + KC) * GUP_COLS;
            pg0 = *(const float4*)gp;
            pg1 = *(const float4*)(gp + 4);
            pu0 = *(const float4*)up;
            pu1 = *(const float4*)(up + 4);
        }
#pragma unroll
        for (int s = 0; s < 2; s++) {
            unsigned ah[4], al[4], ah2[4], al2[4];
            ldsm4(ah,  aOffH + s * 32);
            ldsm4(al,  aOffL + s * 32);
            ldsm4(ah2, aOffH + aT2 + s * 32);
            ldsm4(al2, aOffL + aT2 + s * 32);
            unsigned gh[8], gl[8], uh[8], ul[8];
#pragma unroll
            for (int g = 0; g < 2; g++) {
                uint32_t off = (uint32_t)(s * 16 * SB) * 2 + g * 32;
                ldsm4t(&gh[g * 4], gOffH + off);
                ldsm4t(&gl[g * 4], gOffL + off);
                ldsm4t(&uh[g * 4], uOffH + off);
                ldsm4t(&ul[g * 4], uOffL + off);
            }
#pragma unroll
            for (int t = 0; t < 4; t++) {
                int p = (t >> 1) * 4 + (t & 1) * 2;
                mma_bf16(accG[t],  ah[0],  ah[1],  ah[2],  ah[3],  gh[p], gh[p + 1]);
                mma_bf16(accG[t],  ah[0],  ah[1],  ah[2],  ah[3],  gl[p], gl[p + 1]);
                mma_bf16(accG[t],  al[0],  al[1],  al[2],  al[3],  gh[p], gh[p + 1]);
                mma_bf16(accU[t],  ah[0],  ah[1],  ah[2],  ah[3],  uh[p], uh[p + 1]);
                mma_bf16(accU[t],  ah[0],  ah[1],  ah[2],  ah[3],  ul[p], ul[p + 1]);
                mma_bf16(accU[t],  al[0],  al[1],  al[2],  al[3],  uh[p], uh[p + 1]);
                mma_bf16(accG2[t], ah2[0], ah2[1], ah2[2], ah2[3], gh[p], gh[p + 1]);
                mma_bf16(accG2[t], ah2[0], ah2[1], ah2[2], ah2[3], gl[p], gl[p + 1]);
                mma_bf16(accG2[t], al2[0], al2[1], al2[2], al2[3], gh[p], gh[p + 1]);
                mma_bf16(accU2[t], ah2[0], ah2[1], ah2[2], ah2[3], uh[p], uh[p + 1]);
                mma_bf16(accU2[t], ah2[0], ah2[1], ah2[2], ah2[3], ul[p], ul[p + 1]);
                mma_bf16(accU2[t], al2[0], al2[1], al2[2], al2[3], uh[p], uh[p + 1]);
            }
        }
        __syncthreads();
    }
    const int rw = wm * 16 + gid;
#pragma unroll
    for (int t = 0; t < 4; t++) {
        int c = cb + wn * 32 + t * 8 + tig * 2;
#pragma unroll
        for (int i = 0; i < 2; i++) {
            int r = r0b + rw + i * 8;
            if (r < cnt) {
                float g0 = accG[t][i * 2], u0 = accU[t][i * 2];
                float g1 = accG[t][i * 2 + 1], u1 = accU[t][i * 2 + 1];
                float a0 = (g0 / (1.f + expf(-g0))) * u0;
                float a1 = (g1 / (1.f + expf(-g1))) * u1;
                unsigned h, l;
                f2hl2(a0, a1, h, l);
                *(unsigned*)&g_actr_h[((size_t)e * CAP + r) * I_DIM + c] = h;
                *(unsigned*)&g_actr_l[((size_t)e * CAP + r) * I_DIM + c] = l;
            }
            int r2 = r0b + 64 + rw + i * 8;
            if (r2 < cnt) {
                float g0 = accG2[t][i * 2], u0 = accU2[t][i * 2];
                float g1 = accG2[t][i * 2 + 1], u1 = accU2[t][i * 2 + 1];
                float a0 = (g0 / (1.f + expf(-g0))) * u0;
                float a1 = (g1 / (1.f + expf(-g1))) * u1;
                unsigned h, l;
                f2hl2(a0, a1, h, l);
                *(unsigned*)&g_actr_h[((size_t)e * CAP + r2) * I_DIM + c] = h;
                *(unsigned*)&g_actr_l[((size_t)e * CAP + r2) * I_DIM + c] = l;
            }
        }
    }
}

// ------- routed down: M=128 dual-A-tile, pipelined -------------------------
__global__ __launch_bounds__(256) void routed_down_tc(
    const float* __restrict__ Wall /*[E,512,1024] fp32*/)
{
    const int e = blockIdx.z;
    const int cnt = g_counts[e];
    const int r0b = blockIdx.y * 128;
    if (r0b >= cnt) return;

    __shared__ __align__(16) __nv_bfloat16 sAh[128 * SA], sAl[128 * SA];
    __shared__ __align__(16) __nv_bfloat16 sBh[KC * SB], sBl[KC * SB];

    const int tid = threadIdx.x, lane = tid & 31, wid = tid >> 5;
    const int gid = lane >> 2, tig = lane & 3;
    const int wm = wid & 3, wn = wid >> 2;
    const int cb = blockIdx.x * 64;

    const int ar = tid >> 2, ac8 = (tid & 3) * 8;
    const int bk = tid >> 3, bn8 = (tid & 7) * 8;

    const __nv_bfloat16* aH  = g_actr_h + ((size_t)e * CAP + (r0b + ar)) * I_DIM + ac8;
    const __nv_bfloat16* aL  = g_actr_l + ((size_t)e * CAP + (r0b + ar)) * I_DIM + ac8;
    const __nv_bfloat16* aH2 = aH + (size_t)64 * I_DIM;
    const __nv_bfloat16* aL2 = aL + (size_t)64 * I_DIM;
    const float* bW = Wall + (size_t)e * I_DIM * H_DIM + (size_t)bk * H_DIM + cb + bn8;

    const uint32_t aBase = (uint32_t)((((wm * 16 + (lane & 15)) * SA) + (lane >> 4) * 8) * 2);
    uint32_t aOffH = (uint32_t)__cvta_generic_to_shared(sAh) + aBase;
    uint32_t aOffL = (uint32_t)__cvta_generic_to_shared(sAl) + aBase;
    const uint32_t aT2 = (uint32_t)(64 * SA * 2);
    const int mB = lane >> 3;
    const uint32_t bBase = (uint32_t)(((((mB & 1) * 8 + (lane & 7)) * SB) + wn * 32 + (mB >> 1) * 8) * 2);
    uint32_t bOffH = (uint32_t)__cvta_generic_to_shared(sBh) + bBase;
    uint32_t bOffL = (uint32_t)__cvta_generic_to_shared(sBl) + bBase;

    float acc[4][4] = {}, acc2[4][4] = {};

    uint4  pA0 = *(const uint4*)(aH);
    uint4  pA1 = *(const uint4*)(aL);
    uint4  pA2 = *(const uint4*)(aH2);
    uint4  pA3 = *(const uint4*)(aL2);
    float4 pb0 = *(const float4*)(bW);
    float4 pb1 = *(const float4*)(bW + 4);

    for (int k0 = 0; k0 < I_DIM; k0 += KC) {
        *(uint4*)&sAh[ar * SA + ac8]        = pA0;
        *(uint4*)&sAl[ar * SA + ac8]        = pA1;
        *(uint4*)&sAh[(64 + ar) * SA + ac8] = pA2;
        *(uint4*)&sAl[(64 + ar) * SA + ac8] = pA3;
        {
            unsigned h01, l01, h23, l23;
            f2hl2(pb0.x, pb0.y, h01, l01); f2hl2(pb0.z, pb0.w, h23, l23);
            *(uint2*)&sBh[bk * SB + bn8] = make_uint2(h01, h23);
            *(uint2*)&sBl[bk * SB + bn8] = make_uint2(l01, l23);
            f2hl2(pb1.x, pb1.y, h01, l01); f2hl2(pb1.z, pb1.w, h23, l23);
            *(uint2*)&sBh[bk * SB + bn8 + 4] = make_uint2(h01, h23);
            *(uint2*)&sBl[bk * SB + bn8 + 4] = make_uint2(l01, l23);
        }
        __syncthreads();
        if (k0 + KC < I_DIM) {
            pA0 = *(const uint4*)(aH  + k0 + KC);
            pA1 = *(const uint4*)(aL  + k0 + KC);
            pA2 = *(const uint4*)(aH2 + k0 + KC);
            pA3 = *(const uint4*)(aL2 + k0 + KC);
            const float* bp = bW + (size_t)(k0 + KC) * H_DIM;
            pb0 = *(const float4*)bp;
            pb1 = *(const float4*)(bp + 4);
        }
#pragma unroll
        for (int s = 0; s < 2; s++) {
            unsigned ah[4], al[4], ah2[4], al2[4];
            ldsm4(ah,  aOffH + s * 32);
            ldsm4(al,  aOffL + s * 32);
            ldsm4(ah2, aOffH + aT2 + s * 32);
            ldsm4(al2, aOffL + aT2 + s * 32);
            unsigned bh[8], bl[8];
#pragma unroll
            for (int g = 0; g < 2; g++) {
                uint32_t off = (uint32_t)(s * 16 * SB) * 2 + g * 32;
                ldsm4t(&bh[g * 4], bOffH + off);
                ldsm4t(&bl[g * 4], bOffL + off);
            }
#pragma unroll
            for (int t = 0; t < 4; t++) {
                int p = (t >> 1) * 4 + (t & 1) * 2;
                mma_bf16(acc[t],  ah[0],  ah[1],  ah[2],  ah[3],  bh[p], bh[p + 1]);
                mma_bf16(acc[t],  ah[0],  ah[1],  ah[2],  ah[3],  bl[p], bl[p + 1]);
                mma_bf16(acc[t],  al[0],  al[1],  al[2],  al[3],  bh[p], bh[p + 1]);
                mma_bf16(acc2[t], ah2[0], ah2[1], ah2[2], ah2[3], bh[p], bh[p + 1]);
                mma_bf16(acc2[t], ah2[0], ah2[1], ah2[2], ah2[3], bl[p], bl[p + 1]);
                mma_bf16(acc2[t], al2[0], al2[1], al2[2], al2[3], bh[p], bh[p + 1]);
            }
        }
        __syncthreads();
    }
    const int rw = wm * 16 + gid;
#pragma unroll
    for (int t = 0; t < 4; t++) {
        int c = cb + wn * 32 + t * 8 + tig * 2;
#pragma unroll
        for (int i = 0; i < 2; i++) {
            int r = r0b + rw + i * 8;
            if (r < cnt) {
                int a = g_list[e * CAP + r];
                g_ybuf[(size_t)a * H_DIM + c + 0] = acc[t][i * 2 + 0];
                g_ybuf[(size_t)a * H_DIM + c + 1] = acc[t][i * 2 + 1];
            }
            int r2 = r0b + 64 + rw + i * 8;
            if (r2 < cnt) {
                int a = g_list[e * CAP + r2];
                g_ybuf[(size_t)a * H_DIM + c + 0] = acc2[t][i * 2 + 0];
                g_ybuf[(size_t)a * H_DIM + c + 1] = acc2[t][i * 2 + 1];
            }
        }
    }
}

// ------------------------------- combine -----------------------------------
__global__ __launch_bounds__(256) void combine_kernel(float* __restrict__ out)
{
    const int t = blockIdx.x;
    const int h4 = threadIdx.x * 4;
    float4 o = *(float4*)(out + (size_t)t * H_DIM + h4);
    float r0 = o.x, r1 = o.y, r2 = o.z, r3 = o.w;
#pragma unroll
    for (int k = 0; k < TOPK; k++) {
        int a = t * TOPK + k;
        if (g_keep[a]) {
            float wv = g_w[a] * SCALE_F;
            float4 y = *(const float4*)(g_ybuf + (size_t)a * H_DIM + h4);
            r0 += wv * y.x; r1 += wv * y.y; r2 += wv * y.z; r3 += wv * y.w;
        }
    }
    *(float4*)(out + (size_t)t * H_DIM + h4) = make_float4(r0, r1, r2, r3);
}

// ------------------------------- launcher ----------------------------------
extern "C" void kernel_launch(void* const* d_in, const int* in_sizes, int n_in,
                              void* d_out, int out_size)
{
    const float* x          = (const float*)d_in[0];
    const float* gate_w     = (const float*)d_in[1];
    const float* e_bias     = (const float*)d_in[2];
    const float* w_gate_up  = (const float*)d_in[3];
    const float* w_down     = (const float*)d_in[4];
    const float* ws_gate_up = (const float*)d_in[5];
    const float* ws_down    = (const float*)d_in[6];
    float* out = (float*)d_out;

    __nv_bfloat16 *xs_h, *xs_l, *wsgu_h, *wsgu_l, *wsd_h, *wsd_l;
    cudaGetSymbolAddress((void**)&xs_h, g_xs_h);
    cudaGetSymbolAddress((void**)&xs_l, g_xs_l);
    cudaGetSymbolAddress((void**)&wsgu_h, g_wsgu_h);
    cudaGetSymbolAddress((void**)&wsgu_l, g_wsgu_l);
    cudaGetSymbolAddress((void**)&wsd_h, g_wsd_h);
    cudaGetSymbolAddress((void**)&wsd_l, g_wsd_l);

    auto split = [](const float* s, __nv_bfloat16* h, __nv_bfloat16* l, size_t n) {
        int n4 = (int)(n / 4);
        split_kernel<<<(n4 + 255) / 256, 256>>>((const float4*)s, (uint2*)h, (uint2*)l, n4);
    };

    split(x,          xs_h,   xs_l,   (size_t)T_TOK * H_DIM);
    split(ws_gate_up, wsgu_h, wsgu_l, (size_t)H_DIM * SH_GUP);
    split(ws_down,    wsd_h,  wsd_l,  (size_t)SH_ACT * H_DIM);

    router_kernel<<<T_TOK / 4, 512>>>(x, gate_w, e_bias);
    dispatch_kernel<<<E_EXP, 256>>>();

    shared_gateup_tc<<<dim3(SH_ACT / 64, T_TOK / 64), 256>>>();
    shared_down_tc<<<dim3(H_DIM / 64, T_TOK / 64), 256>>>(out);
    routed_gateup_tc<<<dim3(I_DIM / 64, CAP / 128, E_EXP), 256>>>(w_gate_up);
    routed_down_tc<<<dim3(H_DIM / 64, CAP / 128, E_EXP), 256>>>(w_down);
    combine_kernel<<<T_TOK, 256>>>(out);
}